// round 4
// baseline (speedup 1.0000x reference)
#include <cuda_runtime.h>

// Problem constants
#define Bq   2
#define Sq   2048
#define Dq   768
#define Hq   12
#define HDq  64
#define Mrows (Bq * Sq)   // 4096

// Scratch (device globals: allocation-free)
__device__ float g_Q[Mrows * Dq];
__device__ float g_K[Mrows * Dq];
__device__ float g_V[Mrows * Dq];
__device__ float g_A[Mrows * Dq];

__device__ __forceinline__ float ex2f(float x) {
    float y;
    asm("ex2.approx.ftz.f32 %0, %1;" : "=f"(y) : "f"(x));
    return y;
}

// Packed f32x2 FMA: d = a*b + d (elementwise on 2 packed floats).
__device__ __forceinline__ void fma2(unsigned long long& d,
                                     unsigned long long a,
                                     unsigned long long b) {
    asm("fma.rn.f32x2 %0, %1, %2, %0;" : "+l"(d) : "l"(a), "l"(b));
}
__device__ __forceinline__ float plo(unsigned long long u) {
    return __uint_as_float((unsigned)u);
}
__device__ __forceinline__ float phi(unsigned long long u) {
    return __uint_as_float((unsigned)(u >> 32));
}

// ---------------------------------------------------------------------------
// GEMM: C[M,N] = A[M,K] @ W[K,N] + bias  (M=4096, N=K=768), FFMA2 inner loop.
// 128 x BN CTA tile, 8 x NB micro-tile, BK=16. 256 threads as 16x16 (ty,tx).
// Pairing along k: acc2[a][b] = (even-k partial, odd-k partial).
// blockIdx.z selects among up to 3 independent GEMMs (fused QKV projections).
// ---------------------------------------------------------------------------
struct GemmArgs {
    const float* A[3];
    const float* W[3];
    const float* bias[3];
    float*       C[3];
};

template<int BN, int NB>
__global__ __launch_bounds__(256, 1) void gemm_kernel(GemmArgs args)
{
    constexpr int BK = 16;
    constexpr int BP = BK + 4;  // Bs pitch 20 floats = 5x16B -> conflict-free
    __shared__ __align__(16) float As[128 * BK];
    __shared__ __align__(16) float Bs[BN * BP];

    const int z = blockIdx.z;
    const float* __restrict__ A    = args.A[z];
    const float* __restrict__ W    = args.W[z];
    const float* __restrict__ bias = args.bias[z];
    float* __restrict__ C          = args.C[z];

    const int tid = threadIdx.x;
    const int tx = tid & 15, ty = tid >> 4;
    const int m0 = blockIdx.x * 128, n0 = blockIdx.y * BN;
    const int N = Dq, K = Dq;

    unsigned long long acc2[8][NB];
#pragma unroll
    for (int a = 0; a < 8; a++)
#pragma unroll
        for (int b = 0; b < NB; b++) acc2[a][b] = 0ull;

    for (int k0 = 0; k0 < K; k0 += BK) {
        // A tile: 128x16 floats = 512 float4, 2 per thread (coalesced)
#pragma unroll
        for (int i = 0; i < 2; i++) {
            int idx = tid * 2 + i;
            int m = idx >> 2, kk = (idx & 3) << 2;
            *(float4*)&As[m * BK + kk] =
                *(const float4*)&A[(size_t)(m0 + m) * K + k0 + kk];
        }
        // W tile: 16 x BN, stored transposed as Bs[n][k] (coalesced in n)
#pragma unroll
        for (int e = tid; e < BK * BN; e += 256) {
            int kk = e / BN, n = e % BN;
            Bs[n * BP + kk] = W[(size_t)(k0 + kk) * N + n0 + n];
        }
        __syncthreads();

#pragma unroll
        for (int kk0 = 0; kk0 < BK; kk0 += 4) {
            ulonglong2 ap[8];
#pragma unroll
            for (int a = 0; a < 8; a++)
                ap[a] = *(const ulonglong2*)&As[(ty + 16 * a) * BK + kk0];
#pragma unroll
            for (int b = 0; b < NB; b++) {
                ulonglong2 bp = *(const ulonglong2*)&Bs[(tx + 16 * b) * BP + kk0];
#pragma unroll
                for (int a = 0; a < 8; a++) {
                    fma2(acc2[a][b], ap[a].x, bp.x);
                    fma2(acc2[a][b], ap[a].y, bp.y);
                }
            }
        }
        __syncthreads();
    }

#pragma unroll
    for (int a = 0; a < 8; a++) {
        size_t m = (size_t)(m0 + ty + 16 * a);
#pragma unroll
        for (int b = 0; b < NB; b++) {
            int n = n0 + tx + 16 * b;
            C[m * N + n] = plo(acc2[a][b]) + phi(acc2[a][b]) + bias[n];
        }
    }
}

// ---------------------------------------------------------------------------
// Fused flash attention (fp32, no mask). FFMA2 everywhere.
// Grid: (S/128, H, B). 256 threads as 16x16 (ty,tx).
// QK^T: pairs along d (natural from Qs/Ks rows), two bb-halves of 4 cols.
// PV:   pairs along k — V stored pair-transposed: Vp[kp][c] = (V[2kp][c], V[2kp+1][c]).
// Thread (ty,tx): score rows {ty+16a}, score cols {tx+16bb}, O cols {16j+tx}.
// ---------------------------------------------------------------------------
#define AQT 128
#define QP  68     // Q/K pitch: 17x16B -> conflict-free float4
#define SP  132    // Ss pitch (floats)
#define VP  132    // Vp pitch in floats per kp row (66 pairs x 2)

#define ATTN_SMEM_FLOATS (2 * AQT * QP + 64 * VP + AQT * SP + 3 * AQT)
#define ATTN_SMEM_BYTES  (ATTN_SMEM_FLOATS * 4)

__global__ __launch_bounds__(256, 1) void attn_kernel(
    const float* __restrict__ Qg, const float* __restrict__ Kg,
    const float* __restrict__ Vg, float* __restrict__ Og)
{
    extern __shared__ __align__(16) float sm[];
    float* Qs   = sm;                  // [128][68]   (pre-scaled Q)
    float* Ks   = Qs + AQT * QP;       // [128][68]
    float* Vp   = Ks + AQT * QP;       // [64][132]   pair-transposed V
    float* Ss   = Vp + 64 * VP;        // [128][132]  raw scores -> P
    float* mrow = Ss + AQT * SP;       // [128] running max (base-2 domain)
    float* lrow = mrow + AQT;          // [128] running sum
    float* arow = lrow + AQT;          // [128] rescale factor

    const int tid = threadIdx.x;
    const int tx = tid & 15, ty = tid >> 4;
    const int q0 = blockIdx.x * AQT;
    const int h = blockIdx.y, b = blockIdx.z;
    const size_t base = (size_t)b * Sq * Dq + (size_t)h * HDq;

    const float qscale = 0.125f * 1.4426950408889634f;  // 1/sqrt(64) * log2(e)

    // Load Q tile, pre-scaled
#pragma unroll
    for (int i = 0; i < 8; i++) {
        int idx = tid + 256 * i;
        int r = idx >> 4, c = (idx & 15) << 2;
        float4 q = *(const float4*)&Qg[base + (size_t)(q0 + r) * Dq + c];
        q.x *= qscale; q.y *= qscale; q.z *= qscale; q.w *= qscale;
        *(float4*)&Qs[r * QP + c] = q;
    }
    if (tid < AQT) { mrow[tid] = -1e30f; lrow[tid] = 0.f; }

    float oacc[8][4];
#pragma unroll
    for (int a = 0; a < 8; a++)
#pragma unroll
        for (int j = 0; j < 4; j++) oacc[a][j] = 0.f;

    __syncthreads();

    for (int kt = 0; kt < Sq / AQT; kt++) {
        const int k0g = kt * AQT;
        // Load K tile; load V tile pair-transposed
#pragma unroll
        for (int i = 0; i < 8; i++) {
            int idx = tid + 256 * i;
            int r = idx >> 4, c = (idx & 15) << 2;
            size_t g = base + (size_t)(k0g + r) * Dq + c;
            *(float4*)&Ks[r * QP + c] = *(const float4*)&Kg[g];
            float4 v = *(const float4*)&Vg[g];
            int kp = r >> 1, par = r & 1;
            float* vb = &Vp[kp * VP + c * 2 + par];
            vb[0] = v.x; vb[2] = v.y; vb[4] = v.z; vb[6] = v.w;
        }
        __syncthreads();

        // ---- QK^T with d-paired FFMA2, two halves of 4 cols ----
        float tmax[8];
#pragma unroll
        for (int a = 0; a < 8; a++) tmax[a] = -1e30f;

#pragma unroll
        for (int hh = 0; hh < 2; hh++) {
            unsigned long long s2[8][4];
#pragma unroll
            for (int a = 0; a < 8; a++)
#pragma unroll
                for (int bb = 0; bb < 4; bb++) s2[a][bb] = 0ull;

#pragma unroll
            for (int d0 = 0; d0 < HDq; d0 += 4) {
                ulonglong2 qp[8];
#pragma unroll
                for (int a = 0; a < 8; a++)
                    qp[a] = *(const ulonglong2*)&Qs[(ty + 16 * a) * QP + d0];
#pragma unroll
                for (int bb = 0; bb < 4; bb++) {
                    ulonglong2 kp = *(const ulonglong2*)
                        &Ks[(tx + 16 * (4 * hh + bb)) * QP + d0];
#pragma unroll
                    for (int a = 0; a < 8; a++) {
                        fma2(s2[a][bb], qp[a].x, kp.x);
                        fma2(s2[a][bb], qp[a].y, kp.y);
                    }
                }
            }
#pragma unroll
            for (int a = 0; a < 8; a++) {
#pragma unroll
                for (int bb = 0; bb < 4; bb++) {
                    float s = plo(s2[a][bb]) + phi(s2[a][bb]);
                    tmax[a] = fmaxf(tmax[a], s);
                    Ss[(ty + 16 * a) * SP + tx + 16 * (4 * hh + bb)] = s;
                }
            }
        }

        // ---- running max update (half-warp owns its rows) ----
#pragma unroll
        for (int a = 0; a < 8; a++) {
            float t = tmax[a];
#pragma unroll
            for (int off = 8; off > 0; off >>= 1)
                t = fmaxf(t, __shfl_xor_sync(0xffffffffu, t, off, 16));
            if (tx == 0) {
                int r = ty + 16 * a;
                float mo = mrow[r];
                float mn = fmaxf(mo, t);
                float al = ex2f(mo - mn);
                mrow[r] = mn; arow[r] = al; lrow[r] *= al;
            }
        }
        __syncwarp();

        // ---- exp pass: S -> P in Ss, row sums, rescale O ----
#pragma unroll
        for (int a = 0; a < 8; a++) {
            int r = ty + 16 * a;
            float mn = mrow[r];
            float al = arow[r];
            float sum = 0.f;
#pragma unroll
            for (int bb = 0; bb < 8; bb++) {
                int cix = r * SP + tx + 16 * bb;
                float p = ex2f(Ss[cix] - mn);
                Ss[cix] = p;
                sum += p;
            }
#pragma unroll
            for (int off = 8; off > 0; off >>= 1)
                sum += __shfl_xor_sync(0xffffffffu, sum, off, 16);
            if (tx == 0) lrow[r] += sum;
#pragma unroll
            for (int j = 0; j < 4; j++) oacc[a][j] *= al;
        }
        __syncwarp();

        // ---- PV with k-paired FFMA2 ----
        unsigned long long op[8][4];
#pragma unroll
        for (int a = 0; a < 8; a++)
#pragma unroll
            for (int j = 0; j < 4; j++) op[a][j] = 0ull;

        for (int g = 0; g < 32; g++) {       // 4 k-values per group
            int kk = 4 * g;
            ulonglong2 pp[8];
#pragma unroll
            for (int a = 0; a < 8; a++)
                pp[a] = *(const ulonglong2*)&Ss[(ty + 16 * a) * SP + kk];
#pragma unroll
            for (int j = 0; j < 4; j++) {
                unsigned long long v0 =
                    *(const unsigned long long*)&Vp[(2 * g) * VP + (16 * j + tx) * 2];
                unsigned long long v1 =
                    *(const unsigned long long*)&Vp[(2 * g + 1) * VP + (16 * j + tx) * 2];
#pragma unroll
                for (int a = 0; a < 8; a++) {
                    fma2(op[a][j], pp[a].x, v0);
                    fma2(op[a][j], pp[a].y, v1);
                }
            }
        }
#pragma unroll
        for (int a = 0; a < 8; a++)
#pragma unroll
            for (int j = 0; j < 4; j++)
                oacc[a][j] += plo(op[a][j]) + phi(op[a][j]);

        __syncthreads();   // protect Ks/Vp/Ss before next tile
    }

    // Finalize: divide by l, write [B,S,D] layout
#pragma unroll
    for (int a = 0; a < 8; a++) {
        int r = ty + 16 * a;
        float inv = 1.f / lrow[r];
#pragma unroll
        for (int j = 0; j < 4; j++)
            Og[base + (size_t)(q0 + r) * Dq + 16 * j + tx] = oacc[a][j] * inv;
    }
}

// ---------------------------------------------------------------------------
extern "C" void kernel_launch(void* const* d_in, const int* in_sizes, int n_in,
                              void* d_out, int out_size)
{
    const float* query = (const float*)d_in[0];
    const float* key_  = (const float*)d_in[1];
    const float* value = (const float*)d_in[2];
    const float* Wq = (const float*)d_in[3];
    const float* bq = (const float*)d_in[4];
    const float* Wk = (const float*)d_in[5];
    const float* bk = (const float*)d_in[6];
    const float* Wv = (const float*)d_in[7];
    const float* bv = (const float*)d_in[8];
    const float* Wo = (const float*)d_in[9];
    const float* bo = (const float*)d_in[10];
    float* out = (float*)d_out;

    float *pQ, *pK, *pV, *pA;
    cudaGetSymbolAddress((void**)&pQ, g_Q);
    cudaGetSymbolAddress((void**)&pK, g_K);
    cudaGetSymbolAddress((void**)&pV, g_V);
    cudaGetSymbolAddress((void**)&pA, g_A);

    cudaFuncSetAttribute(attn_kernel,
                         cudaFuncAttributeMaxDynamicSharedMemorySize,
                         ATTN_SMEM_BYTES);

    // Fused Q/K/V projections: one launch, grid.z selects the GEMM (97% fill)
    GemmArgs qkv;
    qkv.A[0] = query; qkv.A[1] = key_; qkv.A[2] = value;
    qkv.W[0] = Wq;    qkv.W[1] = Wk;   qkv.W[2] = Wv;
    qkv.bias[0] = bq; qkv.bias[1] = bk; qkv.bias[2] = bv;
    qkv.C[0] = pQ;    qkv.C[1] = pK;   qkv.C[2] = pV;
    dim3 g3(Mrows / 128, Dq / 128, 3);           // (32, 6, 3) = 576 CTAs
    gemm_kernel<128, 8><<<g3, 256>>>(qkv);

    dim3 ga(Sq / AQT, Hq, Bq);                   // (16, 12, 2) = 384 CTAs
    attn_kernel<<<ga, 256, ATTN_SMEM_BYTES>>>(pQ, pK, pV, pA);

    // Output projection: 128x96 tiles -> 256 CTAs (better single-wave fill)
    GemmArgs og;
    og.A[0] = pA; og.W[0] = Wo; og.bias[0] = bo; og.C[0] = out;
    og.A[1] = og.A[2] = pA; og.W[1] = og.W[2] = Wo;
    og.bias[1] = og.bias[2] = bo; og.C[1] = og.C[2] = out;
    dim3 go(Mrows / 128, Dq / 96, 1);            // (32, 8, 1) = 256 CTAs
    gemm_kernel<96, 6><<<go, 256>>>(og);
}

// round 5
// speedup vs baseline: 1.7951x; 1.7951x over previous
#include <cuda_runtime.h>

// Problem constants
#define Bq   2
#define Sq   2048
#define Dq   768
#define Hq   12
#define HDq  64
#define Mrows (Bq * Sq)   // 4096

// Scratch (device globals: allocation-free)
__device__ float g_Q[Mrows * Dq];
__device__ float g_K[Mrows * Dq];
__device__ float g_V[Mrows * Dq];
__device__ float g_A[Mrows * Dq];

__device__ __forceinline__ float ex2f(float x) {
    float y;
    asm("ex2.approx.ftz.f32 %0, %1;" : "=f"(y) : "f"(x));
    return y;
}

// ---------------------------------------------------------------------------
// GEMM: C[M,N] = A[M,K] @ W[K,N] + bias  (M=4096, N=K=768). Scalar FFMA
// (R3 inner loop — FFMA2 regressed: 248 regs, issue 13.6%).
// 128 x BN CTA tile, 8 x NB micro-tile, BK=16. 256 threads as 16x16 (ty,tx).
// blockIdx.z selects among up to 3 independent GEMMs (fused QKV projections).
// ---------------------------------------------------------------------------
struct GemmArgs {
    const float* A[3];
    const float* W[3];
    const float* bias[3];
    float*       C[3];
};

template<int BN, int NB>
__global__ __launch_bounds__(256, 2) void gemm_kernel(GemmArgs args)
{
    constexpr int BK = 16;
    constexpr int BP = BK + 4;  // Bs pitch 20 floats = 5x16B -> conflict-free f4
    __shared__ __align__(16) float As[128 * BK];
    __shared__ __align__(16) float Bs[BN * BP];

    const int z = blockIdx.z;
    const float* __restrict__ A    = args.A[z];
    const float* __restrict__ W    = args.W[z];
    const float* __restrict__ bias = args.bias[z];
    float* __restrict__ C          = args.C[z];

    const int tid = threadIdx.x;
    const int tx = tid & 15, ty = tid >> 4;
    const int m0 = blockIdx.x * 128, n0 = blockIdx.y * BN;
    const int N = Dq, K = Dq;

    float acc[8][NB];
#pragma unroll
    for (int a = 0; a < 8; a++)
#pragma unroll
        for (int b = 0; b < NB; b++) acc[a][b] = 0.f;

    for (int k0 = 0; k0 < K; k0 += BK) {
        // A tile: 128x16 floats = 512 float4, 2 per thread (coalesced)
#pragma unroll
        for (int i = 0; i < 2; i++) {
            int idx = tid * 2 + i;
            int m = idx >> 2, kk = (idx & 3) << 2;
            *(float4*)&As[m * BK + kk] =
                *(const float4*)&A[(size_t)(m0 + m) * K + k0 + kk];
        }
        // W tile: 16 x BN, stored transposed as Bs[n][k] (coalesced in n)
#pragma unroll
        for (int e = tid; e < BK * BN; e += 256) {
            int kk = e / BN, n = e % BN;
            Bs[n * BP + kk] = W[(size_t)(k0 + kk) * N + n0 + n];
        }
        __syncthreads();

#pragma unroll
        for (int kk = 0; kk < BK; kk += 4) {
            float4 a4[8];
#pragma unroll
            for (int a = 0; a < 8; a++)
                a4[a] = *(const float4*)&As[(ty + 16 * a) * BK + kk]; // broadcast
#pragma unroll
            for (int b = 0; b < NB; b++) {
                float4 b4 = *(const float4*)&Bs[(tx + 16 * b) * BP + kk];
#pragma unroll
                for (int a = 0; a < 8; a++)
                    acc[a][b] += a4[a].x * b4.x + a4[a].y * b4.y +
                                 a4[a].z * b4.z + a4[a].w * b4.w;
            }
        }
        __syncthreads();
    }

#pragma unroll
    for (int a = 0; a < 8; a++) {
        size_t m = (size_t)(m0 + ty + 16 * a);
#pragma unroll
        for (int b = 0; b < NB; b++) {
            int n = n0 + tx + 16 * b;
            C[m * N + n] = acc[a][b] + bias[n];
        }
    }
}

// ---------------------------------------------------------------------------
// Fused flash attention (fp32, no mask — matches reference). R3 version:
// measured 97% of the FFMA-3reg chip ceiling.
// Grid: (S/128, H, B). 256 threads as 16x16.
// Thread (ty,tx): score rows {ty+16a}, score cols {tx+16b}, O cols {4tx..4tx+3}.
// ---------------------------------------------------------------------------
#define AQT 128
#define AKT 128
#define QV_STRIDE 68    // 64 + 4 pad: 16B-row-pitch = 17 -> conflict-free
#define SS_STRIDE 132   // 128 + 4 pad

#define ATTN_SMEM_FLOATS (3 * AQT * QV_STRIDE + AQT * SS_STRIDE + 3 * AQT)
#define ATTN_SMEM_BYTES  (ATTN_SMEM_FLOATS * 4)

__global__ __launch_bounds__(256, 1) void attn_kernel(
    const float* __restrict__ Qg, const float* __restrict__ Kg,
    const float* __restrict__ Vg, float* __restrict__ Og)
{
    extern __shared__ __align__(16) float sm[];
    float* Qs   = sm;                        // [128][68]
    float* Ks   = Qs + AQT * QV_STRIDE;      // [128][68]
    float* Vs   = Ks + AKT * QV_STRIDE;      // [128][68]
    float* Ss   = Vs + AKT * QV_STRIDE;      // [128][132] — P tile
    float* mrow = Ss + AQT * SS_STRIDE;      // [128] running max (base-2 domain)
    float* lrow = mrow + AQT;                // [128] running sum
    float* arow = lrow + AQT;                // [128] rescale factor

    const int tid = threadIdx.x;
    const int tx = tid & 15, ty = tid >> 4;
    const int q0 = blockIdx.x * AQT;
    const int h = blockIdx.y, b = blockIdx.z;
    const size_t base = (size_t)b * Sq * Dq + (size_t)h * HDq;

    // Load Q tile: 128 rows x 64 floats (16 f4/row, coalesced)
#pragma unroll
    for (int i = 0; i < 8; i++) {
        int idx = tid + 256 * i;
        int r = idx >> 4, c = (idx & 15) << 2;
        *(float4*)&Qs[r * QV_STRIDE + c] =
            *(const float4*)&Qg[base + (size_t)(q0 + r) * Dq + c];
    }
    if (tid < AQT) { mrow[tid] = -1e30f; lrow[tid] = 0.f; }

    float oacc[8][4];
#pragma unroll
    for (int a = 0; a < 8; a++)
#pragma unroll
        for (int c = 0; c < 4; c++) oacc[a][c] = 0.f;

    __syncthreads();

    // scale * log2(e): softmax done in base-2 domain
    const float scl = 0.125f * 1.4426950408889634f;

    for (int kt = 0; kt < Sq / AKT; kt++) {
        const int k0 = kt * AKT;
        // Load K and V tiles
#pragma unroll
        for (int i = 0; i < 8; i++) {
            int idx = tid + 256 * i;
            int r = idx >> 4, c = (idx & 15) << 2;
            size_t g = base + (size_t)(k0 + r) * Dq + c;
            *(float4*)&Ks[r * QV_STRIDE + c] = *(const float4*)&Kg[g];
            *(float4*)&Vs[r * QV_STRIDE + c] = *(const float4*)&Vg[g];
        }
        __syncthreads();

        // S = (Q @ K^T) * scl  (kept in registers)
        float sacc[8][8];
#pragma unroll
        for (int a = 0; a < 8; a++)
#pragma unroll
            for (int bb = 0; bb < 8; bb++) sacc[a][bb] = 0.f;

        for (int d0 = 0; d0 < HDq; d0 += 4) {
            float4 a4[8];
#pragma unroll
            for (int a = 0; a < 8; a++)
                a4[a] = *(const float4*)&Qs[(ty + 16 * a) * QV_STRIDE + d0];
#pragma unroll
            for (int bb = 0; bb < 8; bb++) {
                float4 b4 = *(const float4*)&Ks[(tx + 16 * bb) * QV_STRIDE + d0];
#pragma unroll
                for (int a = 0; a < 8; a++)
                    sacc[a][bb] += a4[a].x * b4.x + a4[a].y * b4.y +
                                   a4[a].z * b4.z + a4[a].w * b4.w;
            }
        }

        // Per-row tile max (shfl over the 16 tx lanes of each half-warp),
        // then lane tx==0 updates running max / alpha / scales l.
#pragma unroll
        for (int a = 0; a < 8; a++) {
            float tmax = -1e30f;
#pragma unroll
            for (int bb = 0; bb < 8; bb++) {
                sacc[a][bb] *= scl;
                tmax = fmaxf(tmax, sacc[a][bb]);
            }
#pragma unroll
            for (int off = 8; off > 0; off >>= 1)
                tmax = fmaxf(tmax, __shfl_xor_sync(0xffffffffu, tmax, off, 16));
            if (tx == 0) {
                int r = ty + 16 * a;
                float mo = mrow[r];
                float mn = fmaxf(mo, tmax);
                float al = ex2f(mo - mn);
                mrow[r] = mn; arow[r] = al; lrow[r] *= al;
            }
        }
        // row r is owned entirely by its half-warp (ty = r & 15): warp sync suffices
        __syncwarp();

        // P = exp2(S - m), write P to smem, accumulate row sums, rescale O
#pragma unroll
        for (int a = 0; a < 8; a++) {
            int r = ty + 16 * a;
            float mn = mrow[r];
            float al = arow[r];
            float s = 0.f;
#pragma unroll
            for (int bb = 0; bb < 8; bb++) {
                float p = ex2f(sacc[a][bb] - mn);
                Ss[r * SS_STRIDE + tx + 16 * bb] = p;
                s += p;
            }
#pragma unroll
            for (int off = 8; off > 0; off >>= 1)
                s += __shfl_xor_sync(0xffffffffu, s, off, 16);
            if (tx == 0) lrow[r] += s;
#pragma unroll
            for (int c = 0; c < 4; c++) oacc[a][c] *= al;
        }
        __syncwarp();

        // O += P @ V   (P rows broadcast within half-warp, V f4 conflict-free)
        for (int k = 0; k < AKT; k += 4) {
            float4 v0 = *(const float4*)&Vs[(k + 0) * QV_STRIDE + (tx << 2)];
            float4 v1 = *(const float4*)&Vs[(k + 1) * QV_STRIDE + (tx << 2)];
            float4 v2 = *(const float4*)&Vs[(k + 2) * QV_STRIDE + (tx << 2)];
            float4 v3 = *(const float4*)&Vs[(k + 3) * QV_STRIDE + (tx << 2)];
#pragma unroll
            for (int a = 0; a < 8; a++) {
                float4 p = *(const float4*)&Ss[(ty + 16 * a) * SS_STRIDE + k];
                oacc[a][0] += p.x * v0.x + p.y * v1.x + p.z * v2.x + p.w * v3.x;
                oacc[a][1] += p.x * v0.y + p.y * v1.y + p.z * v2.y + p.w * v3.y;
                oacc[a][2] += p.x * v0.z + p.y * v1.z + p.z * v2.z + p.w * v3.z;
                oacc[a][3] += p.x * v0.w + p.y * v1.w + p.z * v2.w + p.w * v3.w;
            }
        }
        __syncthreads();  // before next tile overwrites Ks/Vs; also publishes lrow
    }

    // Finalize: divide by l, write [B,S,D]-layout attention output
#pragma unroll
    for (int a = 0; a < 8; a++) {
        int r = ty + 16 * a;
        float inv = 1.f / lrow[r];
        float4 o;
        o.x = oacc[a][0] * inv;
        o.y = oacc[a][1] * inv;
        o.z = oacc[a][2] * inv;
        o.w = oacc[a][3] * inv;
        *(float4*)&Og[base + (size_t)(q0 + r) * Dq + (tx << 2)] = o;
    }
}

// ---------------------------------------------------------------------------
extern "C" void kernel_launch(void* const* d_in, const int* in_sizes, int n_in,
                              void* d_out, int out_size)
{
    const float* query = (const float*)d_in[0];
    const float* key_  = (const float*)d_in[1];
    const float* value = (const float*)d_in[2];
    const float* Wq = (const float*)d_in[3];
    const float* bq = (const float*)d_in[4];
    const float* Wk = (const float*)d_in[5];
    const float* bk = (const float*)d_in[6];
    const float* Wv = (const float*)d_in[7];
    const float* bv = (const float*)d_in[8];
    const float* Wo = (const float*)d_in[9];
    const float* bo = (const float*)d_in[10];
    float* out = (float*)d_out;

    float *pQ, *pK, *pV, *pA;
    cudaGetSymbolAddress((void**)&pQ, g_Q);
    cudaGetSymbolAddress((void**)&pK, g_K);
    cudaGetSymbolAddress((void**)&pV, g_V);
    cudaGetSymbolAddress((void**)&pA, g_A);

    cudaFuncSetAttribute(attn_kernel,
                         cudaFuncAttributeMaxDynamicSharedMemorySize,
                         ATTN_SMEM_BYTES);

    // Fused Q/K/V projections: one launch, grid.z selects the GEMM.
    // 576 CTAs over 296 resident slots (2/SM) = 1.94 waves, ~97% fill.
    GemmArgs qkv;
    qkv.A[0] = query; qkv.A[1] = key_; qkv.A[2] = value;
    qkv.W[0] = Wq;    qkv.W[1] = Wk;   qkv.W[2] = Wv;
    qkv.bias[0] = bq; qkv.bias[1] = bk; qkv.bias[2] = bv;
    qkv.C[0] = pQ;    qkv.C[1] = pK;   qkv.C[2] = pV;
    dim3 g3(Mrows / 128, Dq / 128, 3);           // (32, 6, 3) = 576 CTAs
    gemm_kernel<128, 8><<<g3, 256>>>(qkv);

    dim3 ga(Sq / AQT, Hq, Bq);                   // (16, 12, 2) = 384 CTAs
    attn_kernel<<<ga, 256, ATTN_SMEM_BYTES>>>(pQ, pK, pV, pA);

    // Output projection: 128x96 tiles -> 256 CTAs (better single-wave balance:
    // 0.75x work per CTA, max 2 resident per SM -> ~1.5 CTA-times vs 2).
    GemmArgs og;
    og.A[0] = pA; og.W[0] = Wo; og.bias[0] = bo; og.C[0] = out;
    og.A[1] = og.A[2] = pA; og.W[1] = og.W[2] = Wo;
    og.bias[1] = og.bias[2] = bo; og.C[1] = og.C[2] = out;
    dim3 go(Mrows / 128, Dq / 96, 1);            // (32, 8, 1) = 256 CTAs
    gemm_kernel<96, 6><<<go, 256>>>(og);
}

// round 7
// speedup vs baseline: 2.6245x; 1.4620x over previous
#include <cuda_runtime.h>
#include <cuda_bf16.h>
#include <cstdint>

// Problem constants
#define Bq   2
#define Sq   2048
#define Dq   768
#define Hq   12
#define HDq  64
#define Mrows (Bq * Sq)   // 4096
#define K2   1536         // split bf16 K: [hi(768) | lo(768)]

// ---------------- scratch (device globals: allocation-free) ----------------
__device__ float g_Q[Mrows * Dq];
__device__ float g_K[Mrows * Dq];
__device__ float g_V[Mrows * Dq];
__device__ float g_A[Mrows * Dq];
__device__ __nv_bfloat16 g_Isp[3][Mrows * K2];  // split query/key_/value
__device__ __nv_bfloat16 g_Asp[Mrows * K2];     // split attention output
__device__ __nv_bfloat16 g_Wsp[4][Dq * K2];     // split+transposed Wq,Wk,Wv,Wo

__device__ __forceinline__ float ex2f(float x) {
    float y;
    asm("ex2.approx.ftz.f32 %0, %1;" : "=f"(y) : "f"(x));
    return y;
}
__device__ __forceinline__ uint32_t smem_u32(const void* p) {
    uint32_t a;
    asm("{ .reg .u64 t; cvta.to.shared.u64 t, %1; cvt.u32.u64 %0, t; }"
        : "=r"(a) : "l"(p));
    return a;
}

// ---- compute_80-baseline tensor ops (compile under compute_103) -----------
__device__ __forceinline__ void mma16816(float* c, const uint32_t* a,
                                         uint32_t b0, uint32_t b1) {
    asm volatile(
        "mma.sync.aligned.m16n8k16.row.col.f32.bf16.bf16.f32 "
        "{%0,%1,%2,%3}, {%4,%5,%6,%7}, {%8,%9}, {%0,%1,%2,%3};"
        : "+f"(c[0]), "+f"(c[1]), "+f"(c[2]), "+f"(c[3])
        : "r"(a[0]), "r"(a[1]), "r"(a[2]), "r"(a[3]), "r"(b0), "r"(b1));
}
__device__ __forceinline__ void ldsm4(uint32_t* r, uint32_t addr) {
    asm volatile("ldmatrix.sync.aligned.m8n8.x4.shared.b16 {%0,%1,%2,%3}, [%4];"
        : "=r"(r[0]), "=r"(r[1]), "=r"(r[2]), "=r"(r[3]) : "r"(addr));
}
__device__ __forceinline__ void cpasync16(uint32_t saddr, const void* g) {
    asm volatile("cp.async.cg.shared.global [%0], [%1], 16;"
                 :: "r"(saddr), "l"(g) : "memory");
}
#define CP_COMMIT() asm volatile("cp.async.commit_group;" ::: "memory")
#define CP_WAIT(n)  asm volatile("cp.async.wait_group %0;" :: "n"(n) : "memory")

// ---------------------------------------------------------------------------
// Split kernels: fp32 -> [bf16 hi | bf16 lo]  (row-major, K2 = 1536 cols)
// ---------------------------------------------------------------------------
struct SplitInArgs { const float* src[3]; __nv_bfloat16* dst[3]; };

__global__ void split_in_kernel(SplitInArgs a) {
    const float4* src = (const float4*)a.src[blockIdx.z];
    __nv_bfloat16* dst = a.dst[blockIdx.z];
    int idx = blockIdx.x * 256 + threadIdx.x;           // f4 idx, 786432 total
    float4 v = src[idx];
    int r = idx / 192, c = (idx % 192) * 4;
    __nv_bfloat16 h0 = __float2bfloat16(v.x), h1 = __float2bfloat16(v.y);
    __nv_bfloat16 h2 = __float2bfloat16(v.z), h3 = __float2bfloat16(v.w);
    __nv_bfloat16 l0 = __float2bfloat16(v.x - __bfloat162float(h0));
    __nv_bfloat16 l1 = __float2bfloat16(v.y - __bfloat162float(h1));
    __nv_bfloat16 l2 = __float2bfloat16(v.z - __bfloat162float(h2));
    __nv_bfloat16 l3 = __float2bfloat16(v.w - __bfloat162float(h3));
    __nv_bfloat162* dh = (__nv_bfloat162*)&dst[(size_t)r * K2 + c];
    dh[0] = __halves2bfloat162(h0, h1);
    dh[1] = __halves2bfloat162(h2, h3);
    __nv_bfloat162* dl = (__nv_bfloat162*)&dst[(size_t)r * K2 + 768 + c];
    dl[0] = __halves2bfloat162(l0, l1);
    dl[1] = __halves2bfloat162(l2, l3);
}

struct SplitWArgs { const float* W[4]; __nv_bfloat16* Wt[4]; };

// W[k][n] -> Wt[n][hi(768)|lo(768)] via 32x32 smem tile transpose (coalesced
// both sides — R5's version was ~128x line-wasteful on reads).
__global__ void split_w_kernel(SplitWArgs a) {
    __shared__ float t[32][33];
    const float* W = a.W[blockIdx.z];
    __nv_bfloat16* Wt = a.Wt[blockIdx.z];
    int k0 = blockIdx.x * 32, n0 = blockIdx.y * 32;
    int x = threadIdx.x, y0 = threadIdx.y;          // block (32, 8)
#pragma unroll
    for (int j = y0; j < 32; j += 8)
        t[j][x] = W[(size_t)(k0 + j) * Dq + n0 + x];    // t[k][n]
    __syncthreads();
#pragma unroll
    for (int j = y0; j < 32; j += 8) {
        float v = t[x][j];                               // = W[k0+x][n0+j]
        __nv_bfloat16 h = __float2bfloat16(v);
        __nv_bfloat16 l = __float2bfloat16(v - __bfloat162float(h));
        Wt[(size_t)(n0 + j) * K2 + k0 + x] = h;
        Wt[(size_t)(n0 + j) * K2 + 768 + k0 + x] = l;
    }
}

// ---------------------------------------------------------------------------
// HMMA GEMM: C[4096,768] = unsplit(A) @ unsplit(W) + bias.
// A: [4096][1536] bf16 (hi|lo), Wt: [768(N)][1536] bf16 (hi|lo).
// 128x128 CTA tile; 8 warps as 2(m) x 4(n): each warp 64x32 via m16n8k16.
// K loop: 72 iters = 3 segments (hi·hi, lo·hi, hi·lo) x 24 chunks of BK=32.
// cp.async double-buffered smem; 80B row pitch -> conflict-free ldmatrix.
// ---------------------------------------------------------------------------
struct TcGemmArgs {
    const __nv_bfloat16* A[3];
    const __nv_bfloat16* Wt[3];
    const float* bias[3];
    float* C[3];
};

#define PITCH 80                 // bytes per smem row (32 bf16 + 16B pad)
#define ABUF  (128 * PITCH)      // 10240 B per tile

__global__ __launch_bounds__(256) void gemm_tc_kernel(TcGemmArgs args)
{
    __shared__ __align__(16) char sbuf[4 * ABUF];    // A0 B0 A1 B1
    const uint32_t sbase = smem_u32(sbuf);

    const int z = blockIdx.z;
    const __nv_bfloat16* __restrict__ A  = args.A[z];
    const __nv_bfloat16* __restrict__ Wt = args.Wt[z];
    const int tid = threadIdx.x, wid = tid >> 5, lane = tid & 31;
    const int wm = wid & 1, wn = wid >> 1;           // 2 x 4 warp grid
    const int m0 = blockIdx.x * 128, n0 = blockIdx.y * 128;

    float acc[4][4][4];
#pragma unroll
    for (int mt = 0; mt < 4; mt++)
#pragma unroll
        for (int nt = 0; nt < 4; nt++)
#pragma unroll
            for (int i = 0; i < 4; i++) acc[mt][nt][i] = 0.f;

    const int r_ld = tid >> 2, kq = tid & 3;         // 2 rows per thread below

    auto load_chunk = [&](int it, int buf) {
        const int seg = it / 24, c = it % 24;
        const int aoff = ((seg == 1) ? 768 : 0) + c * 32;
        const int boff = ((seg == 2) ? 768 : 0) + c * 32;
        uint32_t sA = sbase + buf * 2 * ABUF;
        uint32_t sB = sA + ABUF;
#pragma unroll
        for (int i = 0; i < 2; i++) {
            int r = r_ld + 64 * i;
            cpasync16(sA + r * PITCH + kq * 16,
                      &A[(size_t)(m0 + r) * K2 + aoff + kq * 8]);
            cpasync16(sB + r * PITCH + kq * 16,
                      &Wt[(size_t)(n0 + r) * K2 + boff + kq * 8]);
        }
    };

    load_chunk(0, 0);
    CP_COMMIT();

    const uint32_t a_off = (uint32_t)((wm * 64 + (lane & 15)) * PITCH +
                                      ((lane >> 4) << 4));
    const uint32_t b_off = (uint32_t)((wn * 32 + (lane & 7) +
                                       ((lane >> 4) << 3)) * PITCH +
                                      (((lane >> 3) & 1) << 4));

    for (int it = 0; it < 72; it++) {
        const int buf = it & 1;
        if (it + 1 < 72) { load_chunk(it + 1, buf ^ 1); CP_COMMIT(); CP_WAIT(1); }
        else             { CP_WAIT(0); }
        __syncthreads();

        uint32_t sA = sbase + buf * 2 * ABUF;
        uint32_t sB = sA + ABUF;
#pragma unroll
        for (int k16 = 0; k16 < 2; k16++) {
            uint32_t af[4][4], bf[2][4];
#pragma unroll
            for (int mt = 0; mt < 4; mt++)
                ldsm4(af[mt], sA + a_off + mt * 16 * PITCH + k16 * 32);
#pragma unroll
            for (int pr = 0; pr < 2; pr++)
                ldsm4(bf[pr], sB + b_off + pr * 16 * PITCH + k16 * 32);
#pragma unroll
            for (int mt = 0; mt < 4; mt++)
#pragma unroll
                for (int pr = 0; pr < 2; pr++) {
                    mma16816(acc[mt][2 * pr],     af[mt], bf[pr][0], bf[pr][1]);
                    mma16816(acc[mt][2 * pr + 1], af[mt], bf[pr][2], bf[pr][3]);
                }
        }
        __syncthreads();
    }

    // Epilogue: direct gmem writes + bias (thread owns rows g, g+8; 2 cols)
    const float* __restrict__ bias = args.bias[z];
    float* __restrict__ C = args.C[z];
    const int g = lane >> 2, tc = (lane & 3) * 2;
#pragma unroll
    for (int mt = 0; mt < 4; mt++) {
        int row0 = m0 + wm * 64 + mt * 16 + g;
#pragma unroll
        for (int nt = 0; nt < 4; nt++) {
            int col = n0 + wn * 32 + nt * 8 + tc;
            float b0 = bias[col], b1 = bias[col + 1];
            float2 v0 = make_float2(acc[mt][nt][0] + b0, acc[mt][nt][1] + b1);
            float2 v1 = make_float2(acc[mt][nt][2] + b0, acc[mt][nt][3] + b1);
            *(float2*)&C[(size_t)row0 * Dq + col] = v0;
            *(float2*)&C[(size_t)(row0 + 8) * Dq + col] = v1;
        }
    }
}

// ---------------------------------------------------------------------------
// Fused flash attention (fp32, no mask) — unchanged R3 kernel (97% of scalar
// FFMA ceiling). Grid: (S/128, H, B). 256 threads as 16x16.
// ---------------------------------------------------------------------------
#define AQT 128
#define AKT 128
#define QV_STRIDE 68
#define SS_STRIDE 132
#define ATTN_SMEM_FLOATS (3 * AQT * QV_STRIDE + AQT * SS_STRIDE + 3 * AQT)
#define ATTN_SMEM_BYTES  (ATTN_SMEM_FLOATS * 4)

__global__ __launch_bounds__(256, 1) void attn_kernel(
    const float* __restrict__ Qg, const float* __restrict__ Kg,
    const float* __restrict__ Vg, float* __restrict__ Og)
{
    extern __shared__ __align__(16) float sm[];
    float* Qs   = sm;
    float* Ks   = Qs + AQT * QV_STRIDE;
    float* Vs   = Ks + AKT * QV_STRIDE;
    float* Ss   = Vs + AKT * QV_STRIDE;
    float* mrow = Ss + AQT * SS_STRIDE;
    float* lrow = mrow + AQT;
    float* arow = lrow + AQT;

    const int tid = threadIdx.x;
    const int tx = tid & 15, ty = tid >> 4;
    const int q0 = blockIdx.x * AQT;
    const int h = blockIdx.y, b = blockIdx.z;
    const size_t base = (size_t)b * Sq * Dq + (size_t)h * HDq;

#pragma unroll
    for (int i = 0; i < 8; i++) {
        int idx = tid + 256 * i;
        int r = idx >> 4, c = (idx & 15) << 2;
        *(float4*)&Qs[r * QV_STRIDE + c] =
            *(const float4*)&Qg[base + (size_t)(q0 + r) * Dq + c];
    }
    if (tid < AQT) { mrow[tid] = -1e30f; lrow[tid] = 0.f; }

    float oacc[8][4];
#pragma unroll
    for (int a = 0; a < 8; a++)
#pragma unroll
        for (int c = 0; c < 4; c++) oacc[a][c] = 0.f;

    __syncthreads();

    const float scl = 0.125f * 1.4426950408889634f;

    for (int kt = 0; kt < Sq / AKT; kt++) {
        const int k0 = kt * AKT;
#pragma unroll
        for (int i = 0; i < 8; i++) {
            int idx = tid + 256 * i;
            int r = idx >> 4, c = (idx & 15) << 2;
            size_t g = base + (size_t)(k0 + r) * Dq + c;
            *(float4*)&Ks[r * QV_STRIDE + c] = *(const float4*)&Kg[g];
            *(float4*)&Vs[r * QV_STRIDE + c] = *(const float4*)&Vg[g];
        }
        __syncthreads();

        float sacc[8][8];
#pragma unroll
        for (int a = 0; a < 8; a++)
#pragma unroll
            for (int bb = 0; bb < 8; bb++) sacc[a][bb] = 0.f;

        for (int d0 = 0; d0 < HDq; d0 += 4) {
            float4 a4[8];
#pragma unroll
            for (int a = 0; a < 8; a++)
                a4[a] = *(const float4*)&Qs[(ty + 16 * a) * QV_STRIDE + d0];
#pragma unroll
            for (int bb = 0; bb < 8; bb++) {
                float4 b4 = *(const float4*)&Ks[(tx + 16 * bb) * QV_STRIDE + d0];
#pragma unroll
                for (int a = 0; a < 8; a++)
                    sacc[a][bb] += a4[a].x * b4.x + a4[a].y * b4.y +
                                   a4[a].z * b4.z + a4[a].w * b4.w;
            }
        }

#pragma unroll
        for (int a = 0; a < 8; a++) {
            float tmax = -1e30f;
#pragma unroll
            for (int bb = 0; bb < 8; bb++) {
                sacc[a][bb] *= scl;
                tmax = fmaxf(tmax, sacc[a][bb]);
            }
#pragma unroll
            for (int off = 8; off > 0; off >>= 1)
                tmax = fmaxf(tmax, __shfl_xor_sync(0xffffffffu, tmax, off, 16));
            if (tx == 0) {
                int r = ty + 16 * a;
                float mo = mrow[r];
                float mn = fmaxf(mo, tmax);
                float al = ex2f(mo - mn);
                mrow[r] = mn; arow[r] = al; lrow[r] *= al;
            }
        }
        __syncwarp();

#pragma unroll
        for (int a = 0; a < 8; a++) {
            int r = ty + 16 * a;
            float mn = mrow[r];
            float al = arow[r];
            float s = 0.f;
#pragma unroll
            for (int bb = 0; bb < 8; bb++) {
                float p = ex2f(sacc[a][bb] - mn);
                Ss[r * SS_STRIDE + tx + 16 * bb] = p;
                s += p;
            }
#pragma unroll
            for (int off = 8; off > 0; off >>= 1)
                s += __shfl_xor_sync(0xffffffffu, s, off, 16);
            if (tx == 0) lrow[r] += s;
#pragma unroll
            for (int c = 0; c < 4; c++) oacc[a][c] *= al;
        }
        __syncwarp();

        for (int k = 0; k < AKT; k += 4) {
            float4 v0 = *(const float4*)&Vs[(k + 0) * QV_STRIDE + (tx << 2)];
            float4 v1 = *(const float4*)&Vs[(k + 1) * QV_STRIDE + (tx << 2)];
            float4 v2 = *(const float4*)&Vs[(k + 2) * QV_STRIDE + (tx << 2)];
            float4 v3 = *(const float4*)&Vs[(k + 3) * QV_STRIDE + (tx << 2)];
#pragma unroll
            for (int a = 0; a < 8; a++) {
                float4 p = *(const float4*)&Ss[(ty + 16 * a) * SS_STRIDE + k];
                oacc[a][0] += p.x * v0.x + p.y * v1.x + p.z * v2.x + p.w * v3.x;
                oacc[a][1] += p.x * v0.y + p.y * v1.y + p.z * v2.y + p.w * v3.y;
                oacc[a][2] += p.x * v0.z + p.y * v1.z + p.z * v2.z + p.w * v3.z;
                oacc[a][3] += p.x * v0.w + p.y * v1.w + p.z * v2.w + p.w * v3.w;
            }
        }
        __syncthreads();
    }

#pragma unroll
    for (int a = 0; a < 8; a++) {
        int r = ty + 16 * a;
        float inv = 1.f / lrow[r];
        float4 o;
        o.x = oacc[a][0] * inv;
        o.y = oacc[a][1] * inv;
        o.z = oacc[a][2] * inv;
        o.w = oacc[a][3] * inv;
        *(float4*)&Og[base + (size_t)(q0 + r) * Dq + (tx << 2)] = o;
    }
}

// ---------------------------------------------------------------------------
extern "C" void kernel_launch(void* const* d_in, const int* in_sizes, int n_in,
                              void* d_out, int out_size)
{
    const float* query = (const float*)d_in[0];
    const float* key_  = (const float*)d_in[1];
    const float* value = (const float*)d_in[2];
    const float* Wq = (const float*)d_in[3];
    const float* bq = (const float*)d_in[4];
    const float* Wk = (const float*)d_in[5];
    const float* bk = (const float*)d_in[6];
    const float* Wv = (const float*)d_in[7];
    const float* bv = (const float*)d_in[8];
    const float* Wo = (const float*)d_in[9];
    const float* bo = (const float*)d_in[10];
    float* out = (float*)d_out;

    float *pQ, *pK, *pV, *pA;
    __nv_bfloat16 *pIsp, *pAsp, *pWsp;
    cudaGetSymbolAddress((void**)&pQ, g_Q);
    cudaGetSymbolAddress((void**)&pK, g_K);
    cudaGetSymbolAddress((void**)&pV, g_V);
    cudaGetSymbolAddress((void**)&pA, g_A);
    cudaGetSymbolAddress((void**)&pIsp, g_Isp);
    cudaGetSymbolAddress((void**)&pAsp, g_Asp);
    cudaGetSymbolAddress((void**)&pWsp, g_Wsp);

    cudaFuncSetAttribute(attn_kernel,
                         cudaFuncAttributeMaxDynamicSharedMemorySize,
                         ATTN_SMEM_BYTES);

    // 1) split inputs (query/key_/value) -> bf16 hi|lo
    SplitInArgs si;
    si.src[0] = query; si.src[1] = key_; si.src[2] = value;
    si.dst[0] = pIsp;  si.dst[1] = pIsp + (size_t)Mrows * K2;
    si.dst[2] = pIsp + 2 * (size_t)Mrows * K2;
    split_in_kernel<<<dim3(3072, 1, 3), 256>>>(si);

    // 2) split + transpose weights (tile transpose, coalesced)
    SplitWArgs sw;
    sw.W[0] = Wq; sw.W[1] = Wk; sw.W[2] = Wv; sw.W[3] = Wo;
    for (int i = 0; i < 4; i++) sw.Wt[i] = pWsp + (size_t)i * Dq * K2;
    split_w_kernel<<<dim3(24, 24, 4), dim3(32, 8)>>>(sw);

    // 3) QKV projections (HMMA)
    TcGemmArgs qkv;
    for (int i = 0; i < 3; i++) {
        qkv.A[i]  = pIsp + (size_t)i * Mrows * K2;
        qkv.Wt[i] = pWsp + (size_t)i * Dq * K2;
    }
    qkv.bias[0] = bq; qkv.bias[1] = bk; qkv.bias[2] = bv;
    qkv.C[0] = pQ;    qkv.C[1] = pK;    qkv.C[2] = pV;
    gemm_tc_kernel<<<dim3(Mrows / 128, Dq / 128, 3), 256>>>(qkv);

    // 4) attention (scalar fp32)
    dim3 ga(Sq / AQT, Hq, Bq);
    attn_kernel<<<ga, 256, ATTN_SMEM_BYTES>>>(pQ, pK, pV, pA);

    // 5) split attention output
    SplitInArgs sa;
    sa.src[0] = pA; sa.dst[0] = pAsp;
    sa.src[1] = pA; sa.dst[1] = pAsp;   // unused (z-grid = 1)
    sa.src[2] = pA; sa.dst[2] = pAsp;
    split_in_kernel<<<dim3(3072, 1, 1), 256>>>(sa);

    // 6) output projection (HMMA)
    TcGemmArgs og;
    og.A[0] = pAsp; og.Wt[0] = pWsp + 3 * (size_t)Dq * K2;
    og.bias[0] = bo; og.C[0] = out;
    og.A[1] = og.A[2] = pAsp; og.Wt[1] = og.Wt[2] = og.Wt[0];
    og.bias[1] = og.bias[2] = bo; og.C[1] = og.C[2] = out;
    gemm_tc_kernel<<<dim3(Mrows / 128, Dq / 128, 1), 256>>>(og);
}

// round 9
// speedup vs baseline: 4.9499x; 1.8860x over previous
#include <cuda_runtime.h>
#include <cuda_bf16.h>
#include <cstdint>

// Problem constants
#define Bq   2
#define Sq   2048
#define Dq   768
#define Hq   12
#define HDq  64
#define Mrows (Bq * Sq)   // 4096
#define K2   1536         // split bf16 K: [hi(768) | lo(768)]

// ---------------- scratch (device globals: allocation-free) ----------------
__device__ float g_Q[Mrows * Dq];
__device__ float g_K[Mrows * Dq];
__device__ float g_V[Mrows * Dq];
__device__ __nv_bfloat16 g_Isp[3][Mrows * K2];  // split query/key_/value
__device__ __nv_bfloat16 g_Asp[Mrows * K2];     // split attention output
__device__ __nv_bfloat16 g_Wsp[4][Dq * K2];     // split+transposed Wq,Wk,Wv,Wo

__device__ __forceinline__ float ex2f(float x) {
    float y;
    asm("ex2.approx.ftz.f32 %0, %1;" : "=f"(y) : "f"(x));
    return y;
}
__device__ __forceinline__ uint32_t smem_u32(const void* p) {
    uint32_t a;
    asm("{ .reg .u64 t; cvta.to.shared.u64 t, %1; cvt.u32.u64 %0, t; }"
        : "=r"(a) : "l"(p));
    return a;
}
__device__ __forceinline__ uint32_t packbf(float x, float y) {
    __nv_bfloat162 t = __floats2bfloat162_rn(x, y);   // .x = low half
    return *(uint32_t*)&t;
}
__device__ __forceinline__ float2 unpackbf(uint32_t u) {
    __nv_bfloat162 t = *(__nv_bfloat162*)&u;
    return __bfloat1622float2(t);
}

// ---- compute_80-baseline tensor ops (compile under compute_103) -----------
__device__ __forceinline__ void mma16816(float* c, const uint32_t* a,
                                         uint32_t b0, uint32_t b1) {
    asm volatile(
        "mma.sync.aligned.m16n8k16.row.col.f32.bf16.bf16.f32 "
        "{%0,%1,%2,%3}, {%4,%5,%6,%7}, {%8,%9}, {%0,%1,%2,%3};"
        : "+f"(c[0]), "+f"(c[1]), "+f"(c[2]), "+f"(c[3])
        : "r"(a[0]), "r"(a[1]), "r"(a[2]), "r"(a[3]), "r"(b0), "r"(b1));
}
__device__ __forceinline__ void ldsm4(uint32_t* r, uint32_t addr) {
    asm volatile("ldmatrix.sync.aligned.m8n8.x4.shared.b16 {%0,%1,%2,%3}, [%4];"
        : "=r"(r[0]), "=r"(r[1]), "=r"(r[2]), "=r"(r[3]) : "r"(addr));
}
__device__ __forceinline__ void cpasync16(uint32_t saddr, const void* g) {
    asm volatile("cp.async.cg.shared.global [%0], [%1], 16;"
                 :: "r"(saddr), "l"(g) : "memory");
}
#define CP_COMMIT() asm volatile("cp.async.commit_group;" ::: "memory")
#define CP_WAIT(n)  asm volatile("cp.async.wait_group %0;" :: "n"(n) : "memory")

// ---------------------------------------------------------------------------
// Split kernels: fp32 -> [bf16 hi | bf16 lo]  (row-major, K2 = 1536 cols)
// ---------------------------------------------------------------------------
struct SplitInArgs { const float* src[3]; __nv_bfloat16* dst[3]; };

__global__ void split_in_kernel(SplitInArgs a) {
    const float4* src = (const float4*)a.src[blockIdx.z];
    __nv_bfloat16* dst = a.dst[blockIdx.z];
    int idx = blockIdx.x * 256 + threadIdx.x;           // f4 idx, 786432 total
    float4 v = src[idx];
    int r = idx / 192, c = (idx % 192) * 4;
    __nv_bfloat16 h0 = __float2bfloat16(v.x), h1 = __float2bfloat16(v.y);
    __nv_bfloat16 h2 = __float2bfloat16(v.z), h3 = __float2bfloat16(v.w);
    __nv_bfloat16 l0 = __float2bfloat16(v.x - __bfloat162float(h0));
    __nv_bfloat16 l1 = __float2bfloat16(v.y - __bfloat162float(h1));
    __nv_bfloat16 l2 = __float2bfloat16(v.z - __bfloat162float(h2));
    __nv_bfloat16 l3 = __float2bfloat16(v.w - __bfloat162float(h3));
    __nv_bfloat162* dh = (__nv_bfloat162*)&dst[(size_t)r * K2 + c];
    dh[0] = __halves2bfloat162(h0, h1);
    dh[1] = __halves2bfloat162(h2, h3);
    __nv_bfloat162* dl = (__nv_bfloat162*)&dst[(size_t)r * K2 + 768 + c];
    dl[0] = __halves2bfloat162(l0, l1);
    dl[1] = __halves2bfloat162(l2, l3);
}

struct SplitWArgs { const float* W[4]; __nv_bfloat16* Wt[4]; };

// W[k][n] -> Wt[n][hi(768)|lo(768)] via 32x32 smem tile transpose.
__global__ void split_w_kernel(SplitWArgs a) {
    __shared__ float t[32][33];
    const float* W = a.W[blockIdx.z];
    __nv_bfloat16* Wt = a.Wt[blockIdx.z];
    int k0 = blockIdx.x * 32, n0 = blockIdx.y * 32;
    int x = threadIdx.x, y0 = threadIdx.y;          // block (32, 8)
#pragma unroll
    for (int j = y0; j < 32; j += 8)
        t[j][x] = W[(size_t)(k0 + j) * Dq + n0 + x];
    __syncthreads();
#pragma unroll
    for (int j = y0; j < 32; j += 8) {
        float v = t[x][j];
        __nv_bfloat16 h = __float2bfloat16(v);
        __nv_bfloat16 l = __float2bfloat16(v - __bfloat162float(h));
        Wt[(size_t)(n0 + j) * K2 + k0 + x] = h;
        Wt[(size_t)(n0 + j) * K2 + 768 + k0 + x] = l;
    }
}

// ---------------------------------------------------------------------------
// HMMA GEMM (validated R7): C[4096,768] = unsplit(A) @ unsplit(W) + bias.
// ---------------------------------------------------------------------------
struct TcGemmArgs {
    const __nv_bfloat16* A[3];
    const __nv_bfloat16* Wt[3];
    const float* bias[3];
    float* C[3];
};

#define PITCH 80
#define ABUF  (128 * PITCH)

__global__ __launch_bounds__(256) void gemm_tc_kernel(TcGemmArgs args)
{
    __shared__ __align__(16) char sbuf[4 * ABUF];
    const uint32_t sbase = smem_u32(sbuf);

    const int z = blockIdx.z;
    const __nv_bfloat16* __restrict__ A  = args.A[z];
    const __nv_bfloat16* __restrict__ Wt = args.Wt[z];
    const int tid = threadIdx.x, wid = tid >> 5, lane = tid & 31;
    const int wm = wid & 1, wn = wid >> 1;
    const int m0 = blockIdx.x * 128, n0 = blockIdx.y * 128;

    float acc[4][4][4];
#pragma unroll
    for (int mt = 0; mt < 4; mt++)
#pragma unroll
        for (int nt = 0; nt < 4; nt++)
#pragma unroll
            for (int i = 0; i < 4; i++) acc[mt][nt][i] = 0.f;

    const int r_ld = tid >> 2, kq = tid & 3;

    auto load_chunk = [&](int it, int buf) {
        const int seg = it / 24, c = it % 24;
        const int aoff = ((seg == 1) ? 768 : 0) + c * 32;
        const int boff = ((seg == 2) ? 768 : 0) + c * 32;
        uint32_t sA = sbase + buf * 2 * ABUF;
        uint32_t sB = sA + ABUF;
#pragma unroll
        for (int i = 0; i < 2; i++) {
            int r = r_ld + 64 * i;
            cpasync16(sA + r * PITCH + kq * 16,
                      &A[(size_t)(m0 + r) * K2 + aoff + kq * 8]);
            cpasync16(sB + r * PITCH + kq * 16,
                      &Wt[(size_t)(n0 + r) * K2 + boff + kq * 8]);
        }
    };

    load_chunk(0, 0);
    CP_COMMIT();

    const uint32_t a_off = (uint32_t)((wm * 64 + (lane & 15)) * PITCH +
                                      ((lane >> 4) << 4));
    const uint32_t b_off = (uint32_t)((wn * 32 + (lane & 7) +
                                       ((lane >> 4) << 3)) * PITCH +
                                      (((lane >> 3) & 1) << 4));

    for (int it = 0; it < 72; it++) {
        const int buf = it & 1;
        if (it + 1 < 72) { load_chunk(it + 1, buf ^ 1); CP_COMMIT(); CP_WAIT(1); }
        else             { CP_WAIT(0); }
        __syncthreads();

        uint32_t sA = sbase + buf * 2 * ABUF;
        uint32_t sB = sA + ABUF;
#pragma unroll
        for (int k16 = 0; k16 < 2; k16++) {
            uint32_t af[4][4], bf[2][4];
#pragma unroll
            for (int mt = 0; mt < 4; mt++)
                ldsm4(af[mt], sA + a_off + mt * 16 * PITCH + k16 * 32);
#pragma unroll
            for (int pr = 0; pr < 2; pr++)
                ldsm4(bf[pr], sB + b_off + pr * 16 * PITCH + k16 * 32);
#pragma unroll
            for (int mt = 0; mt < 4; mt++)
#pragma unroll
                for (int pr = 0; pr < 2; pr++) {
                    mma16816(acc[mt][2 * pr],     af[mt], bf[pr][0], bf[pr][1]);
                    mma16816(acc[mt][2 * pr + 1], af[mt], bf[pr][2], bf[pr][3]);
                }
        }
        __syncthreads();
    }

    const float* __restrict__ bias = args.bias[z];
    float* __restrict__ C = args.C[z];
    const int g = lane >> 2, tc = (lane & 3) * 2;
#pragma unroll
    for (int mt = 0; mt < 4; mt++) {
        int row0 = m0 + wm * 64 + mt * 16 + g;
#pragma unroll
        for (int nt = 0; nt < 4; nt++) {
            int col = n0 + wn * 32 + nt * 8 + tc;
            float b0 = bias[col], b1 = bias[col + 1];
            float2 v0 = make_float2(acc[mt][nt][0] + b0, acc[mt][nt][1] + b1);
            float2 v1 = make_float2(acc[mt][nt][2] + b0, acc[mt][nt][3] + b1);
            *(float2*)&C[(size_t)row0 * Dq + col] = v0;
            *(float2*)&C[(size_t)(row0 + 8) * Dq + col] = v1;
        }
    }
}

// ---------------------------------------------------------------------------
// HMMA flash attention with split-bf16 precision.
// Grid (S/128, H, B), 256 threads = 8 warps; warp w owns rows w*16..w*16+15
// of the 128-query tile, full 128 key cols -> softmax reduces in quads only.
// QK^T: Qh·Kh + Ql·Kh + Qh·Kl   (Q pre-scaled by 0.125*log2e)
// P:    exp2 in registers; C-frag -> A-frag identity; split into Ph/Pl.
// PV:   Ph·Vh + Pl·Vh + Ph·Vl   (V transposed+split to Vt[n][k] in smem)
// Output written directly as split bf16 into g_Asp (O-proj input layout).
// ---------------------------------------------------------------------------
#define QPB 72     // halves per Q/K smem row (144 B = 9x16B, odd -> ldsm-safe)
#define VPB 136    // halves per Vt smem row (272 B = 17x16B)
#define ATTN2_SMEM ((4 * 128 * QPB + 2 * 64 * VPB) * 2)   // 108544 B

__global__ __launch_bounds__(256, 1) void attn_tc_kernel(
    const float* __restrict__ Qg, const float* __restrict__ Kg,
    const float* __restrict__ Vg, __nv_bfloat16* __restrict__ Osp)
{
    extern __shared__ __align__(16) char dsm[];
    __nv_bfloat16* const QH = (__nv_bfloat16*)dsm;
    __nv_bfloat16* const QL = QH + 128 * QPB;
    __nv_bfloat16* const KH = QL + 128 * QPB;
    __nv_bfloat16* const KL = KH + 128 * QPB;
    __nv_bfloat16* const VH = KL + 128 * QPB;
    __nv_bfloat16* const VL = VH + 64 * VPB;
    const uint32_t uQH = smem_u32(QH), uQL = smem_u32(QL);
    const uint32_t uKH = smem_u32(KH), uKL = smem_u32(KL);
    const uint32_t uVH = smem_u32(VH), uVL = smem_u32(VL);

    const int tid = threadIdx.x, lane = tid & 31, wid = tid >> 5;
    const int g = lane >> 2, t = lane & 3;
    const int q0 = blockIdx.x * 128;
    const int h = blockIdx.y, b = blockIdx.z;
    const size_t base = (size_t)b * Sq * Dq + (size_t)h * HDq;

    const float scl2 = 0.125f * 1.4426950408889634f;

    // Q tile -> scaled split bf16 (once per CTA)
#pragma unroll
    for (int i = 0; i < 8; i++) {
        int idx = tid + 256 * i;
        int r = idx >> 4, c = (idx & 15) << 2;
        float4 q = *(const float4*)&Qg[base + (size_t)(q0 + r) * Dq + c];
        q.x *= scl2; q.y *= scl2; q.z *= scl2; q.w *= scl2;
        uint32_t h01 = packbf(q.x, q.y), h23 = packbf(q.z, q.w);
        float2 f0 = unpackbf(h01), f1 = unpackbf(h23);
        *(uint32_t*)&QH[r * QPB + c]     = h01;
        *(uint32_t*)&QH[r * QPB + c + 2] = h23;
        *(uint32_t*)&QL[r * QPB + c]     = packbf(q.x - f0.x, q.y - f0.y);
        *(uint32_t*)&QL[r * QPB + c + 2] = packbf(q.z - f1.x, q.w - f1.y);
    }

    float m0 = -1e30f, m1 = -1e30f, l0 = 0.f, l1 = 0.f;
    float oacc[8][4];
#pragma unroll
    for (int nt = 0; nt < 8; nt++)
#pragma unroll
        for (int i = 0; i < 4; i++) oacc[nt][i] = 0.f;

    const uint32_t a_off  = (uint32_t)((wid * 16 + (lane & 15)) * 144 +
                                       ((lane >> 4) << 4));
    const uint32_t kb_off = (uint32_t)(((lane & 7) + ((lane >> 4) << 3)) * 144 +
                                       (((lane >> 3) & 1) << 4));
    const uint32_t vb_off = (uint32_t)(((lane & 7) + ((lane >> 4) << 3)) * 272 +
                                       (((lane >> 3) & 1) << 4));
    __syncthreads();

    for (int kt = 0; kt < 16; kt++) {
        const int k0 = kt * 128;
        // K tile -> split bf16 [key][d]
#pragma unroll
        for (int i = 0; i < 8; i++) {
            int idx = tid + 256 * i;
            int r = idx >> 4, c = (idx & 15) << 2;
            float4 kv = *(const float4*)&Kg[base + (size_t)(k0 + r) * Dq + c];
            uint32_t h01 = packbf(kv.x, kv.y), h23 = packbf(kv.z, kv.w);
            float2 f0 = unpackbf(h01), f1 = unpackbf(h23);
            *(uint32_t*)&KH[r * QPB + c]     = h01;
            *(uint32_t*)&KH[r * QPB + c + 2] = h23;
            *(uint32_t*)&KL[r * QPB + c]     = packbf(kv.x - f0.x, kv.y - f0.y);
            *(uint32_t*)&KL[r * QPB + c + 2] = packbf(kv.z - f1.x, kv.w - f1.y);
        }
        // V tile -> transposed split bf16 Vt[d][key] (2x2 cells per thread-iter)
#pragma unroll
        for (int i = 0; i < 8; i++) {
            int cc = tid + 256 * i;                     // 2048 cells
            int r = (cc >> 5) * 2, c = (cc & 31) * 2;
            float2 va = *(const float2*)&Vg[base + (size_t)(k0 + r) * Dq + c];
            float2 vb = *(const float2*)&Vg[base + (size_t)(k0 + r + 1) * Dq + c];
            uint32_t h0 = packbf(va.x, vb.x);           // col c, keys r,r+1
            uint32_t h1 = packbf(va.y, vb.y);           // col c+1
            float2 f0 = unpackbf(h0), f1 = unpackbf(h1);
            *(uint32_t*)&VH[c * VPB + r]       = h0;
            *(uint32_t*)&VH[(c + 1) * VPB + r] = h1;
            *(uint32_t*)&VL[c * VPB + r]       = packbf(va.x - f0.x, vb.x - f0.y);
            *(uint32_t*)&VL[(c + 1) * VPB + r] = packbf(va.y - f1.x, vb.y - f1.y);
        }
        __syncthreads();

        // ---- QK^T (3 split passes) ----
        float sacc[16][4];
#pragma unroll
        for (int nt = 0; nt < 16; nt++)
#pragma unroll
            for (int i = 0; i < 4; i++) sacc[nt][i] = 0.f;

#pragma unroll
        for (int ps = 0; ps < 3; ps++) {
            uint32_t uA = (ps == 1) ? uQL : uQH;
            uint32_t uB = (ps == 2) ? uKL : uKH;
#pragma unroll
            for (int j = 0; j < 4; j++) {
                uint32_t af[4];
                ldsm4(af, uA + a_off + j * 32);
#pragma unroll
                for (int p = 0; p < 8; p++) {
                    uint32_t bf4[4];
                    ldsm4(bf4, uB + kb_off + p * (16 * 144) + j * 32);
                    mma16816(sacc[2 * p],     af, bf4[0], bf4[1]);
                    mma16816(sacc[2 * p + 1], af, bf4[2], bf4[3]);
                }
            }
        }

        // ---- softmax (registers; rows owned by quads) ----
        float tmax0 = -1e30f, tmax1 = -1e30f;
#pragma unroll
        for (int nt = 0; nt < 16; nt++) {
            tmax0 = fmaxf(tmax0, fmaxf(sacc[nt][0], sacc[nt][1]));
            tmax1 = fmaxf(tmax1, fmaxf(sacc[nt][2], sacc[nt][3]));
        }
        tmax0 = fmaxf(tmax0, __shfl_xor_sync(0xffffffffu, tmax0, 1));
        tmax0 = fmaxf(tmax0, __shfl_xor_sync(0xffffffffu, tmax0, 2));
        tmax1 = fmaxf(tmax1, __shfl_xor_sync(0xffffffffu, tmax1, 1));
        tmax1 = fmaxf(tmax1, __shfl_xor_sync(0xffffffffu, tmax1, 2));
        float mn0 = fmaxf(m0, tmax0), mn1 = fmaxf(m1, tmax1);
        float al0 = ex2f(m0 - mn0),  al1 = ex2f(m1 - mn1);
        m0 = mn0; m1 = mn1;
        float s0 = 0.f, s1 = 0.f;
#pragma unroll
        for (int nt = 0; nt < 16; nt++) {
            sacc[nt][0] = ex2f(sacc[nt][0] - m0); s0 += sacc[nt][0];
            sacc[nt][1] = ex2f(sacc[nt][1] - m0); s0 += sacc[nt][1];
            sacc[nt][2] = ex2f(sacc[nt][2] - m1); s1 += sacc[nt][2];
            sacc[nt][3] = ex2f(sacc[nt][3] - m1); s1 += sacc[nt][3];
        }
        s0 += __shfl_xor_sync(0xffffffffu, s0, 1);
        s0 += __shfl_xor_sync(0xffffffffu, s0, 2);
        s1 += __shfl_xor_sync(0xffffffffu, s1, 1);
        s1 += __shfl_xor_sync(0xffffffffu, s1, 2);
        l0 = l0 * al0 + s0;
        l1 = l1 * al1 + s1;
#pragma unroll
        for (int nt = 0; nt < 8; nt++) {
            oacc[nt][0] *= al0; oacc[nt][1] *= al0;
            oacc[nt][2] *= al1; oacc[nt][3] *= al1;
        }

        // ---- P C-frag -> bf16 A-frags (hi/lo) in registers ----
        uint32_t Ph[8][4], Pl[8][4];
#pragma unroll
        for (int j = 0; j < 8; j++) {
            uint32_t u; float2 f;
            u = packbf(sacc[2*j][0], sacc[2*j][1]); Ph[j][0] = u;
            f = unpackbf(u);
            Pl[j][0] = packbf(sacc[2*j][0] - f.x, sacc[2*j][1] - f.y);
            u = packbf(sacc[2*j][2], sacc[2*j][3]); Ph[j][1] = u;
            f = unpackbf(u);
            Pl[j][1] = packbf(sacc[2*j][2] - f.x, sacc[2*j][3] - f.y);
            u = packbf(sacc[2*j+1][0], sacc[2*j+1][1]); Ph[j][2] = u;
            f = unpackbf(u);
            Pl[j][2] = packbf(sacc[2*j+1][0] - f.x, sacc[2*j+1][1] - f.y);
            u = packbf(sacc[2*j+1][2], sacc[2*j+1][3]); Ph[j][3] = u;
            f = unpackbf(u);
            Pl[j][3] = packbf(sacc[2*j+1][2] - f.x, sacc[2*j+1][3] - f.y);
        }

        // ---- PV (3 split passes) ----
#pragma unroll
        for (int ps = 0; ps < 3; ps++) {
            uint32_t uB = (ps == 2) ? uVL : uVH;
#pragma unroll
            for (int j = 0; j < 8; j++) {
                const uint32_t* PA = (ps == 1) ? Pl[j] : Ph[j];
#pragma unroll
                for (int p = 0; p < 4; p++) {
                    uint32_t bf4[4];
                    ldsm4(bf4, uB + vb_off + p * (16 * 272) + j * 32);
                    mma16816(oacc[2 * p],     PA, bf4[0], bf4[1]);
                    mma16816(oacc[2 * p + 1], PA, bf4[2], bf4[3]);
                }
            }
        }
        __syncthreads();   // protect K/V smem before next tile's converts
    }

    // ---- finalize: write split bf16 directly into O-proj input layout ----
    // Global row includes the batch offset (R8 bug: b*Sq was missing).
    const int r0 = b * Sq + q0 + wid * 16 + g, r1 = r0 + 8;
    const float inv0 = 1.f / l0, inv1 = 1.f / l1;
#pragma unroll
    for (int nt = 0; nt < 8; nt++) {
        int col = h * 64 + nt * 8 + t * 2;
        float o00 = oacc[nt][0] * inv0, o01 = oacc[nt][1] * inv0;
        float o10 = oacc[nt][2] * inv1, o11 = oacc[nt][3] * inv1;
        uint32_t hi0 = packbf(o00, o01);
        float2 f0 = unpackbf(hi0);
        uint32_t lo0 = packbf(o00 - f0.x, o01 - f0.y);
        uint32_t hi1 = packbf(o10, o11);
        float2 f1 = unpackbf(hi1);
        uint32_t lo1 = packbf(o10 - f1.x, o11 - f1.y);
        *(uint32_t*)&Osp[(size_t)r0 * K2 + col]       = hi0;
        *(uint32_t*)&Osp[(size_t)r0 * K2 + 768 + col] = lo0;
        *(uint32_t*)&Osp[(size_t)r1 * K2 + col]       = hi1;
        *(uint32_t*)&Osp[(size_t)r1 * K2 + 768 + col] = lo1;
    }
}

// ---------------------------------------------------------------------------
extern "C" void kernel_launch(void* const* d_in, const int* in_sizes, int n_in,
                              void* d_out, int out_size)
{
    const float* query = (const float*)d_in[0];
    const float* key_  = (const float*)d_in[1];
    const float* value = (const float*)d_in[2];
    const float* Wq = (const float*)d_in[3];
    const float* bq = (const float*)d_in[4];
    const float* Wk = (const float*)d_in[5];
    const float* bk = (const float*)d_in[6];
    const float* Wv = (const float*)d_in[7];
    const float* bv = (const float*)d_in[8];
    const float* Wo = (const float*)d_in[9];
    const float* bo = (const float*)d_in[10];
    float* out = (float*)d_out;

    float *pQ, *pK, *pV;
    __nv_bfloat16 *pIsp, *pAsp, *pWsp;
    cudaGetSymbolAddress((void**)&pQ, g_Q);
    cudaGetSymbolAddress((void**)&pK, g_K);
    cudaGetSymbolAddress((void**)&pV, g_V);
    cudaGetSymbolAddress((void**)&pIsp, g_Isp);
    cudaGetSymbolAddress((void**)&pAsp, g_Asp);
    cudaGetSymbolAddress((void**)&pWsp, g_Wsp);

    cudaFuncSetAttribute(attn_tc_kernel,
                         cudaFuncAttributeMaxDynamicSharedMemorySize,
                         ATTN2_SMEM);

    // 1) split inputs -> bf16 hi|lo
    SplitInArgs si;
    si.src[0] = query; si.src[1] = key_; si.src[2] = value;
    si.dst[0] = pIsp;  si.dst[1] = pIsp + (size_t)Mrows * K2;
    si.dst[2] = pIsp + 2 * (size_t)Mrows * K2;
    split_in_kernel<<<dim3(3072, 1, 3), 256>>>(si);

    // 2) split + transpose weights
    SplitWArgs sw;
    sw.W[0] = Wq; sw.W[1] = Wk; sw.W[2] = Wv; sw.W[3] = Wo;
    for (int i = 0; i < 4; i++) sw.Wt[i] = pWsp + (size_t)i * Dq * K2;
    split_w_kernel<<<dim3(24, 24, 4), dim3(32, 8)>>>(sw);

    // 3) QKV projections (HMMA)
    TcGemmArgs qkv;
    for (int i = 0; i < 3; i++) {
        qkv.A[i]  = pIsp + (size_t)i * Mrows * K2;
        qkv.Wt[i] = pWsp + (size_t)i * Dq * K2;
    }
    qkv.bias[0] = bq; qkv.bias[1] = bk; qkv.bias[2] = bv;
    qkv.C[0] = pQ;    qkv.C[1] = pK;    qkv.C[2] = pV;
    gemm_tc_kernel<<<dim3(Mrows / 128, Dq / 128, 3), 256>>>(qkv);

    // 4) attention (HMMA, split precision) -> writes split bf16 directly
    dim3 ga(Sq / 128, Hq, Bq);
    attn_tc_kernel<<<ga, 256, ATTN2_SMEM>>>(pQ, pK, pV, pAsp);

    // 5) output projection (HMMA)
    TcGemmArgs og;
    og.A[0] = pAsp; og.Wt[0] = pWsp + 3 * (size_t)Dq * K2;
    og.bias[0] = bo; og.C[0] = out;
    og.A[1] = og.A[2] = pAsp; og.Wt[1] = og.Wt[2] = og.Wt[0];
    og.bias[1] = og.bias[2] = bo; og.C[1] = og.C[2] = og.C[0];
    gemm_tc_kernel<<<dim3(Mrows / 128, Dq / 128, 1), 256>>>(og);
}

// round 10
// speedup vs baseline: 5.6496x; 1.1414x over previous
#include <cuda_runtime.h>
#include <cuda_bf16.h>
#include <cstdint>

// Problem constants
#define Bq   2
#define Sq   2048
#define Dq   768
#define Hq   12
#define HDq  64
#define Mrows (Bq * Sq)   // 4096
#define K2   1536         // split bf16 K: [hi(768) | lo(768)]
#define BH   (Bq * Hq)    // 24

// ---------------- scratch (device globals: allocation-free) ----------------
__device__ float g_Q[Mrows * Dq];
__device__ float g_K[Mrows * Dq];
__device__ float g_V[Mrows * Dq];
__device__ __nv_bfloat16 g_Isp[3][Mrows * K2];  // split query/key_/value
__device__ __nv_bfloat16 g_Asp[Mrows * K2];     // split attention output
__device__ __nv_bfloat16 g_Wsp[4][Dq * K2];     // split+transposed Wq,Wk,Wv,Wo
// Pre-split attention operands (per (b,h) plane)
__device__ __nv_bfloat16 g_KspH[BH * Sq * HDq]; // K hi  [bh][s][d]
__device__ __nv_bfloat16 g_KspL[BH * Sq * HDq]; // K lo
__device__ __nv_bfloat16 g_VtH[BH * HDq * Sq];  // V^T hi [bh][d][s]
__device__ __nv_bfloat16 g_VtL[BH * HDq * Sq];  // V^T lo

__device__ __forceinline__ float ex2f(float x) {
    float y;
    asm("ex2.approx.ftz.f32 %0, %1;" : "=f"(y) : "f"(x));
    return y;
}
__device__ __forceinline__ uint32_t smem_u32(const void* p) {
    uint32_t a;
    asm("{ .reg .u64 t; cvta.to.shared.u64 t, %1; cvt.u32.u64 %0, t; }"
        : "=r"(a) : "l"(p));
    return a;
}
__device__ __forceinline__ uint32_t packbf(float x, float y) {
    __nv_bfloat162 t = __floats2bfloat162_rn(x, y);   // .x = low half
    return *(uint32_t*)&t;
}
__device__ __forceinline__ float2 unpackbf(uint32_t u) {
    __nv_bfloat162 t = *(__nv_bfloat162*)&u;
    return __bfloat1622float2(t);
}

// ---- compute_80-baseline tensor ops (compile under compute_103) -----------
__device__ __forceinline__ void mma16816(float* c, const uint32_t* a,
                                         uint32_t b0, uint32_t b1) {
    asm volatile(
        "mma.sync.aligned.m16n8k16.row.col.f32.bf16.bf16.f32 "
        "{%0,%1,%2,%3}, {%4,%5,%6,%7}, {%8,%9}, {%0,%1,%2,%3};"
        : "+f"(c[0]), "+f"(c[1]), "+f"(c[2]), "+f"(c[3])
        : "r"(a[0]), "r"(a[1]), "r"(a[2]), "r"(a[3]), "r"(b0), "r"(b1));
}
__device__ __forceinline__ void ldsm4(uint32_t* r, uint32_t addr) {
    asm volatile("ldmatrix.sync.aligned.m8n8.x4.shared.b16 {%0,%1,%2,%3}, [%4];"
        : "=r"(r[0]), "=r"(r[1]), "=r"(r[2]), "=r"(r[3]) : "r"(addr));
}
__device__ __forceinline__ void cpasync16(uint32_t saddr, const void* g) {
    asm volatile("cp.async.cg.shared.global [%0], [%1], 16;"
                 :: "r"(saddr), "l"(g) : "memory");
}
#define CP_COMMIT() asm volatile("cp.async.commit_group;" ::: "memory")
#define CP_WAIT(n)  asm volatile("cp.async.wait_group %0;" :: "n"(n) : "memory")

// ---------------------------------------------------------------------------
// Split kernels: fp32 -> [bf16 hi | bf16 lo]  (row-major, K2 = 1536 cols)
// ---------------------------------------------------------------------------
struct SplitInArgs { const float* src[3]; __nv_bfloat16* dst[3]; };

__global__ void split_in_kernel(SplitInArgs a) {
    const float4* src = (const float4*)a.src[blockIdx.z];
    __nv_bfloat16* dst = a.dst[blockIdx.z];
    int idx = blockIdx.x * 256 + threadIdx.x;           // f4 idx, 786432 total
    float4 v = src[idx];
    int r = idx / 192, c = (idx % 192) * 4;
    __nv_bfloat16 h0 = __float2bfloat16(v.x), h1 = __float2bfloat16(v.y);
    __nv_bfloat16 h2 = __float2bfloat16(v.z), h3 = __float2bfloat16(v.w);
    __nv_bfloat16 l0 = __float2bfloat16(v.x - __bfloat162float(h0));
    __nv_bfloat16 l1 = __float2bfloat16(v.y - __bfloat162float(h1));
    __nv_bfloat16 l2 = __float2bfloat16(v.z - __bfloat162float(h2));
    __nv_bfloat16 l3 = __float2bfloat16(v.w - __bfloat162float(h3));
    __nv_bfloat162* dh = (__nv_bfloat162*)&dst[(size_t)r * K2 + c];
    dh[0] = __halves2bfloat162(h0, h1);
    dh[1] = __halves2bfloat162(h2, h3);
    __nv_bfloat162* dl = (__nv_bfloat162*)&dst[(size_t)r * K2 + 768 + c];
    dl[0] = __halves2bfloat162(l0, l1);
    dl[1] = __halves2bfloat162(l2, l3);
}

struct SplitWArgs { const float* W[4]; __nv_bfloat16* Wt[4]; };

// W[k][n] -> Wt[n][hi(768)|lo(768)] via 32x32 smem tile transpose.
__global__ void split_w_kernel(SplitWArgs a) {
    __shared__ float t[32][33];
    const float* W = a.W[blockIdx.z];
    __nv_bfloat16* Wt = a.Wt[blockIdx.z];
    int k0 = blockIdx.x * 32, n0 = blockIdx.y * 32;
    int x = threadIdx.x, y0 = threadIdx.y;          // block (32, 8)
#pragma unroll
    for (int j = y0; j < 32; j += 8)
        t[j][x] = W[(size_t)(k0 + j) * Dq + n0 + x];
    __syncthreads();
#pragma unroll
    for (int j = y0; j < 32; j += 8) {
        float v = t[x][j];
        __nv_bfloat16 h = __float2bfloat16(v);
        __nv_bfloat16 l = __float2bfloat16(v - __bfloat162float(h));
        Wt[(size_t)(n0 + j) * K2 + k0 + x] = h;
        Wt[(size_t)(n0 + j) * K2 + 768 + k0 + x] = l;
    }
}

// K fp32 [b][s][D] (head slice) -> per-plane split bf16 [bh][s][64]
__global__ void split_k_kernel(const float* __restrict__ Kf,
                               __nv_bfloat16* __restrict__ H,
                               __nv_bfloat16* __restrict__ L) {
    int idx = blockIdx.x * 256 + threadIdx.x;       // 786432 f4
    int bh = idx >> 15, rem = idx & 32767;
    int s = rem >> 4, d = (rem & 15) << 2;
    int b = bh / Hq, h = bh % Hq;
    float4 v = *(const float4*)&Kf[(size_t)(b * Sq + s) * Dq + h * HDq + d];
    size_t off = (size_t)bh * Sq * HDq + s * HDq + d;
    uint32_t h01 = packbf(v.x, v.y), h23 = packbf(v.z, v.w);
    float2 f0 = unpackbf(h01), f1 = unpackbf(h23);
    *(uint32_t*)&H[off]     = h01;
    *(uint32_t*)&H[off + 2] = h23;
    *(uint32_t*)&L[off]     = packbf(v.x - f0.x, v.y - f0.y);
    *(uint32_t*)&L[off + 2] = packbf(v.z - f1.x, v.w - f1.y);
}

// V fp32 [b][s][D] (head slice) -> transposed split bf16 [bh][d][s]
__global__ void transpose_v_kernel(const float* __restrict__ Vf,
                                   __nv_bfloat16* __restrict__ H,
                                   __nv_bfloat16* __restrict__ L) {
    __shared__ float t[32][33];
    int bh = blockIdx.z, b = bh / Hq, h = bh % Hq;
    int s0 = blockIdx.x * 32, d0 = blockIdx.y * 32;
    int x = threadIdx.x, y0 = threadIdx.y;          // block (32, 8)
#pragma unroll
    for (int j = y0; j < 32; j += 8)
        t[j][x] = Vf[(size_t)(b * Sq + s0 + j) * Dq + h * HDq + d0 + x];
    __syncthreads();
#pragma unroll
    for (int j = y0; j < 32; j += 8) {
        float v = t[x][j];                          // = V[s0+x][d0+j]
        __nv_bfloat16 hh = __float2bfloat16(v);
        __nv_bfloat16 ll = __float2bfloat16(v - __bfloat162float(hh));
        size_t off = (size_t)bh * HDq * Sq + (size_t)(d0 + j) * Sq + s0 + x;
        H[off] = hh;
        L[off] = ll;
    }
}

// ---------------------------------------------------------------------------
// HMMA GEMM (validated R7): C[4096,768] = unsplit(A) @ unsplit(W) + bias.
// ---------------------------------------------------------------------------
struct TcGemmArgs {
    const __nv_bfloat16* A[3];
    const __nv_bfloat16* Wt[3];
    const float* bias[3];
    float* C[3];
};

#define PITCH 80
#define ABUF  (128 * PITCH)

__global__ __launch_bounds__(256) void gemm_tc_kernel(TcGemmArgs args)
{
    __shared__ __align__(16) char sbuf[4 * ABUF];
    const uint32_t sbase = smem_u32(sbuf);

    const int z = blockIdx.z;
    const __nv_bfloat16* __restrict__ A  = args.A[z];
    const __nv_bfloat16* __restrict__ Wt = args.Wt[z];
    const int tid = threadIdx.x, wid = tid >> 5, lane = tid & 31;
    const int wm = wid & 1, wn = wid >> 1;
    const int m0 = blockIdx.x * 128, n0 = blockIdx.y * 128;

    float acc[4][4][4];
#pragma unroll
    for (int mt = 0; mt < 4; mt++)
#pragma unroll
        for (int nt = 0; nt < 4; nt++)
#pragma unroll
            for (int i = 0; i < 4; i++) acc[mt][nt][i] = 0.f;

    const int r_ld = tid >> 2, kq = tid & 3;

    auto load_chunk = [&](int it, int buf) {
        const int seg = it / 24, c = it % 24;
        const int aoff = ((seg == 1) ? 768 : 0) + c * 32;
        const int boff = ((seg == 2) ? 768 : 0) + c * 32;
        uint32_t sA = sbase + buf * 2 * ABUF;
        uint32_t sB = sA + ABUF;
#pragma unroll
        for (int i = 0; i < 2; i++) {
            int r = r_ld + 64 * i;
            cpasync16(sA + r * PITCH + kq * 16,
                      &A[(size_t)(m0 + r) * K2 + aoff + kq * 8]);
            cpasync16(sB + r * PITCH + kq * 16,
                      &Wt[(size_t)(n0 + r) * K2 + boff + kq * 8]);
        }
    };

    load_chunk(0, 0);
    CP_COMMIT();

    const uint32_t a_off = (uint32_t)((wm * 64 + (lane & 15)) * PITCH +
                                      ((lane >> 4) << 4));
    const uint32_t b_off = (uint32_t)((wn * 32 + (lane & 7) +
                                       ((lane >> 4) << 3)) * PITCH +
                                      (((lane >> 3) & 1) << 4));

    for (int it = 0; it < 72; it++) {
        const int buf = it & 1;
        if (it + 1 < 72) { load_chunk(it + 1, buf ^ 1); CP_COMMIT(); CP_WAIT(1); }
        else             { CP_WAIT(0); }
        __syncthreads();

        uint32_t sA = sbase + buf * 2 * ABUF;
        uint32_t sB = sA + ABUF;
#pragma unroll
        for (int k16 = 0; k16 < 2; k16++) {
            uint32_t af[4][4], bf[2][4];
#pragma unroll
            for (int mt = 0; mt < 4; mt++)
                ldsm4(af[mt], sA + a_off + mt * 16 * PITCH + k16 * 32);
#pragma unroll
            for (int pr = 0; pr < 2; pr++)
                ldsm4(bf[pr], sB + b_off + pr * 16 * PITCH + k16 * 32);
#pragma unroll
            for (int mt = 0; mt < 4; mt++)
#pragma unroll
                for (int pr = 0; pr < 2; pr++) {
                    mma16816(acc[mt][2 * pr],     af[mt], bf[pr][0], bf[pr][1]);
                    mma16816(acc[mt][2 * pr + 1], af[mt], bf[pr][2], bf[pr][3]);
                }
        }
        __syncthreads();
    }

    const float* __restrict__ bias = args.bias[z];
    float* __restrict__ C = args.C[z];
    const int g = lane >> 2, tc = (lane & 3) * 2;
#pragma unroll
    for (int mt = 0; mt < 4; mt++) {
        int row0 = m0 + wm * 64 + mt * 16 + g;
#pragma unroll
        for (int nt = 0; nt < 4; nt++) {
            int col = n0 + wn * 32 + nt * 8 + tc;
            float b0 = bias[col], b1 = bias[col + 1];
            float2 v0 = make_float2(acc[mt][nt][0] + b0, acc[mt][nt][1] + b1);
            float2 v1 = make_float2(acc[mt][nt][2] + b0, acc[mt][nt][3] + b1);
            *(float2*)&C[(size_t)row0 * Dq + col] = v0;
            *(float2*)&C[(size_t)(row0 + 8) * Dq + col] = v1;
        }
    }
}

// ---------------------------------------------------------------------------
// HMMA flash attention, split-bf16, with PRE-SPLIT K/V (cp.async double-
// buffered) and interleaved P-conversion (low register pressure).
// Grid (S/128, H, B), 256 threads = 8 warps; warp w owns q rows w*16..+15.
// ---------------------------------------------------------------------------
#define QPB 72     // halves per Q/K smem row (144 B = 9x16B, odd -> ldsm-safe)
#define VPB 136    // halves per Vt smem row (272 B = 17x16B)
// halves: Q hi+lo = 2*128*72 = 18432 ; per buf: K 18432 + V 2*64*136 = 17408
#define BUF_HALVES (18432 + 17408)
#define ATTN3_SMEM ((18432 + 2 * BUF_HALVES) * 2)   // 180224 B

__global__ __launch_bounds__(256, 1) void attn_tc_kernel(
    const float* __restrict__ Qg,
    const __nv_bfloat16* __restrict__ KspH, const __nv_bfloat16* __restrict__ KspL,
    const __nv_bfloat16* __restrict__ VtH,  const __nv_bfloat16* __restrict__ VtL,
    __nv_bfloat16* __restrict__ Osp)
{
    extern __shared__ __align__(16) char dsm[];
    __nv_bfloat16* const QH = (__nv_bfloat16*)dsm;
    __nv_bfloat16* const QL = QH + 128 * QPB;
    const uint32_t uQH = smem_u32(QH), uQL = smem_u32(QL);
    const uint32_t uBUF0 = uQH + 18432 * 2;          // byte addr of buffer 0

    const int tid = threadIdx.x, lane = tid & 31, wid = tid >> 5;
    const int g = lane >> 2, t = lane & 3;
    const int q0 = blockIdx.x * 128;
    const int h = blockIdx.y, b = blockIdx.z;
    const int bh = b * Hq + h;
    const size_t base = (size_t)b * Sq * Dq + (size_t)h * HDq;
    const __nv_bfloat16* kH = KspH + (size_t)bh * Sq * HDq;
    const __nv_bfloat16* kL = KspL + (size_t)bh * Sq * HDq;
    const __nv_bfloat16* vH = VtH + (size_t)bh * HDq * Sq;
    const __nv_bfloat16* vL = VtL + (size_t)bh * HDq * Sq;

    const float scl2 = 0.125f * 1.4426950408889634f;

    // Issue first K/V tile loads before converting Q (overlap).
    auto loadKV = [&](int kt, int buf) {
        const int k0 = kt * 128;
        const uint32_t ub = uBUF0 + buf * (BUF_HALVES * 2);
        const uint32_t uKH = ub, uKL = ub + 18432;
        const uint32_t uVH = ub + 36864, uVL = ub + 36864 + 17408;
        // K: 1024 chunks/plane (128 rows x 8), 4 per thread per plane
#pragma unroll
        for (int i = 0; i < 4; i++) {
            int id = tid + 256 * i;
            int r = id >> 3, c = id & 7;
            cpasync16(uKH + r * 144 + c * 16, &kH[(size_t)(k0 + r) * HDq + c * 8]);
            cpasync16(uKL + r * 144 + c * 16, &kL[(size_t)(k0 + r) * HDq + c * 8]);
        }
        // V: 1024 chunks/plane (64 rows x 16), 4 per thread per plane
#pragma unroll
        for (int i = 0; i < 4; i++) {
            int id = tid + 256 * i;
            int r = id >> 4, c = id & 15;
            cpasync16(uVH + r * 272 + c * 16, &vH[(size_t)r * Sq + k0 + c * 8]);
            cpasync16(uVL + r * 272 + c * 16, &vL[(size_t)r * Sq + k0 + c * 8]);
        }
    };

    loadKV(0, 0);
    CP_COMMIT();

    // Q tile -> scaled split bf16 (once per CTA)
#pragma unroll
    for (int i = 0; i < 8; i++) {
        int idx = tid + 256 * i;
        int r = idx >> 4, c = (idx & 15) << 2;
        float4 q = *(const float4*)&Qg[base + (size_t)(q0 + r) * Dq + c];
        q.x *= scl2; q.y *= scl2; q.z *= scl2; q.w *= scl2;
        uint32_t h01 = packbf(q.x, q.y), h23 = packbf(q.z, q.w);
        float2 f0 = unpackbf(h01), f1 = unpackbf(h23);
        *(uint32_t*)&QH[r * QPB + c]     = h01;
        *(uint32_t*)&QH[r * QPB + c + 2] = h23;
        *(uint32_t*)&QL[r * QPB + c]     = packbf(q.x - f0.x, q.y - f0.y);
        *(uint32_t*)&QL[r * QPB + c + 2] = packbf(q.z - f1.x, q.w - f1.y);
    }

    float m0 = -1e30f, m1 = -1e30f, l0 = 0.f, l1 = 0.f;
    float oacc[8][4];
#pragma unroll
    for (int nt = 0; nt < 8; nt++)
#pragma unroll
        for (int i = 0; i < 4; i++) oacc[nt][i] = 0.f;

    const uint32_t a_off  = (uint32_t)((wid * 16 + (lane & 15)) * 144 +
                                       ((lane >> 4) << 4));
    const uint32_t kb_off = (uint32_t)(((lane & 7) + ((lane >> 4) << 3)) * 144 +
                                       (((lane >> 3) & 1) << 4));
    const uint32_t vb_off = (uint32_t)(((lane & 7) + ((lane >> 4) << 3)) * 272 +
                                       (((lane >> 3) & 1) << 4));

    for (int kt = 0; kt < 16; kt++) {
        const int buf = kt & 1;
        if (kt + 1 < 16) { loadKV(kt + 1, buf ^ 1); CP_COMMIT(); CP_WAIT(1); }
        else             { CP_WAIT(0); }
        __syncthreads();

        const uint32_t ub = uBUF0 + buf * (BUF_HALVES * 2);
        const uint32_t uKH = ub, uKL = ub + 18432;
        const uint32_t uVH = ub + 36864, uVL = ub + 36864 + 17408;

        // ---- QK^T: j-outer, Q frags loaded once per j ----
        float sacc[16][4];
#pragma unroll
        for (int nt = 0; nt < 16; nt++)
#pragma unroll
            for (int i = 0; i < 4; i++) sacc[nt][i] = 0.f;

#pragma unroll
        for (int j = 0; j < 4; j++) {
            uint32_t ah[4], al[4];
            ldsm4(ah, uQH + a_off + j * 32);
            ldsm4(al, uQL + a_off + j * 32);
#pragma unroll
            for (int p = 0; p < 8; p++) {
                uint32_t bh4[4], bl4[4];
                ldsm4(bh4, uKH + kb_off + p * (16 * 144) + j * 32);
                ldsm4(bl4, uKL + kb_off + p * (16 * 144) + j * 32);
                mma16816(sacc[2 * p],     ah, bh4[0], bh4[1]);
                mma16816(sacc[2 * p + 1], ah, bh4[2], bh4[3]);
                mma16816(sacc[2 * p],     al, bh4[0], bh4[1]);
                mma16816(sacc[2 * p + 1], al, bh4[2], bh4[3]);
                mma16816(sacc[2 * p],     ah, bl4[0], bl4[1]);
                mma16816(sacc[2 * p + 1], ah, bl4[2], bl4[3]);
            }
        }

        // ---- softmax (registers; rows owned by quads) ----
        float tmax0 = -1e30f, tmax1 = -1e30f;
#pragma unroll
        for (int nt = 0; nt < 16; nt++) {
            tmax0 = fmaxf(tmax0, fmaxf(sacc[nt][0], sacc[nt][1]));
            tmax1 = fmaxf(tmax1, fmaxf(sacc[nt][2], sacc[nt][3]));
        }
        tmax0 = fmaxf(tmax0, __shfl_xor_sync(0xffffffffu, tmax0, 1));
        tmax0 = fmaxf(tmax0, __shfl_xor_sync(0xffffffffu, tmax0, 2));
        tmax1 = fmaxf(tmax1, __shfl_xor_sync(0xffffffffu, tmax1, 1));
        tmax1 = fmaxf(tmax1, __shfl_xor_sync(0xffffffffu, tmax1, 2));
        float mn0 = fmaxf(m0, tmax0), mn1 = fmaxf(m1, tmax1);
        float al0 = ex2f(m0 - mn0),  al1 = ex2f(m1 - mn1);
        m0 = mn0; m1 = mn1;
        float s0 = 0.f, s1 = 0.f;
#pragma unroll
        for (int nt = 0; nt < 16; nt++) {
            sacc[nt][0] = ex2f(sacc[nt][0] - m0); s0 += sacc[nt][0];
            sacc[nt][1] = ex2f(sacc[nt][1] - m0); s0 += sacc[nt][1];
            sacc[nt][2] = ex2f(sacc[nt][2] - m1); s1 += sacc[nt][2];
            sacc[nt][3] = ex2f(sacc[nt][3] - m1); s1 += sacc[nt][3];
        }
        s0 += __shfl_xor_sync(0xffffffffu, s0, 1);
        s0 += __shfl_xor_sync(0xffffffffu, s0, 2);
        s1 += __shfl_xor_sync(0xffffffffu, s1, 1);
        s1 += __shfl_xor_sync(0xffffffffu, s1, 2);
        l0 = l0 * al0 + s0;
        l1 = l1 * al1 + s1;
#pragma unroll
        for (int nt = 0; nt < 8; nt++) {
            oacc[nt][0] *= al0; oacc[nt][1] *= al0;
            oacc[nt][2] *= al1; oacc[nt][3] *= al1;
        }

        // ---- PV: j-outer, P converted per-j (8 live P regs) ----
#pragma unroll
        for (int j = 0; j < 8; j++) {
            uint32_t Ph[4], Pl[4];
            {
                uint32_t u; float2 f;
                u = packbf(sacc[2*j][0], sacc[2*j][1]); Ph[0] = u;
                f = unpackbf(u);
                Pl[0] = packbf(sacc[2*j][0] - f.x, sacc[2*j][1] - f.y);
                u = packbf(sacc[2*j][2], sacc[2*j][3]); Ph[1] = u;
                f = unpackbf(u);
                Pl[1] = packbf(sacc[2*j][2] - f.x, sacc[2*j][3] - f.y);
                u = packbf(sacc[2*j+1][0], sacc[2*j+1][1]); Ph[2] = u;
                f = unpackbf(u);
                Pl[2] = packbf(sacc[2*j+1][0] - f.x, sacc[2*j+1][1] - f.y);
                u = packbf(sacc[2*j+1][2], sacc[2*j+1][3]); Ph[3] = u;
                f = unpackbf(u);
                Pl[3] = packbf(sacc[2*j+1][2] - f.x, sacc[2*j+1][3] - f.y);
            }
#pragma unroll
            for (int p = 0; p < 4; p++) {
                uint32_t vh4[4], vl4[4];
                ldsm4(vh4, uVH + vb_off + p * (16 * 272) + j * 32);
                ldsm4(vl4, uVL + vb_off + p * (16 * 272) + j * 32);
                mma16816(oacc[2 * p],     Ph, vh4[0], vh4[1]);
                mma16816(oacc[2 * p + 1], Ph, vh4[2], vh4[3]);
                mma16816(oacc[2 * p],     Pl, vh4[0], vh4[1]);
                mma16816(oacc[2 * p + 1], Pl, vh4[2], vh4[3]);
                mma16816(oacc[2 * p],     Ph, vl4[0], vl4[1]);
                mma16816(oacc[2 * p + 1], Ph, vl4[2], vl4[3]);
            }
        }
        __syncthreads();   // buffer reuse safety before next tile's cp.asyncs
    }

    // ---- finalize: write split bf16 directly into O-proj input layout ----
    const int r0 = b * Sq + q0 + wid * 16 + g, r1 = r0 + 8;
    const float inv0 = 1.f / l0, inv1 = 1.f / l1;
#pragma unroll
    for (int nt = 0; nt < 8; nt++) {
        int col = h * 64 + nt * 8 + t * 2;
        float o00 = oacc[nt][0] * inv0, o01 = oacc[nt][1] * inv0;
        float o10 = oacc[nt][2] * inv1, o11 = oacc[nt][3] * inv1;
        uint32_t hi0 = packbf(o00, o01);
        float2 f0 = unpackbf(hi0);
        uint32_t lo0 = packbf(o00 - f0.x, o01 - f0.y);
        uint32_t hi1 = packbf(o10, o11);
        float2 f1 = unpackbf(hi1);
        uint32_t lo1 = packbf(o10 - f1.x, o11 - f1.y);
        *(uint32_t*)&Osp[(size_t)r0 * K2 + col]       = hi0;
        *(uint32_t*)&Osp[(size_t)r0 * K2 + 768 + col] = lo0;
        *(uint32_t*)&Osp[(size_t)r1 * K2 + col]       = hi1;
        *(uint32_t*)&Osp[(size_t)r1 * K2 + 768 + col] = lo1;
    }
}

// ---------------------------------------------------------------------------
extern "C" void kernel_launch(void* const* d_in, const int* in_sizes, int n_in,
                              void* d_out, int out_size)
{
    const float* query = (const float*)d_in[0];
    const float* key_  = (const float*)d_in[1];
    const float* value = (const float*)d_in[2];
    const float* Wq = (const float*)d_in[3];
    const float* bq = (const float*)d_in[4];
    const float* Wk = (const float*)d_in[5];
    const float* bk = (const float*)d_in[6];
    const float* Wv = (const float*)d_in[7];
    const float* bv = (const float*)d_in[8];
    const float* Wo = (const float*)d_in[9];
    const float* bo = (const float*)d_in[10];
    float* out = (float*)d_out;

    float *pQ, *pK, *pV;
    __nv_bfloat16 *pIsp, *pAsp, *pWsp, *pKH, *pKL, *pVH, *pVL;
    cudaGetSymbolAddress((void**)&pQ, g_Q);
    cudaGetSymbolAddress((void**)&pK, g_K);
    cudaGetSymbolAddress((void**)&pV, g_V);
    cudaGetSymbolAddress((void**)&pIsp, g_Isp);
    cudaGetSymbolAddress((void**)&pAsp, g_Asp);
    cudaGetSymbolAddress((void**)&pWsp, g_Wsp);
    cudaGetSymbolAddress((void**)&pKH, g_KspH);
    cudaGetSymbolAddress((void**)&pKL, g_KspL);
    cudaGetSymbolAddress((void**)&pVH, g_VtH);
    cudaGetSymbolAddress((void**)&pVL, g_VtL);

    cudaFuncSetAttribute(attn_tc_kernel,
                         cudaFuncAttributeMaxDynamicSharedMemorySize,
                         ATTN3_SMEM);

    // 1) split inputs -> bf16 hi|lo
    SplitInArgs si;
    si.src[0] = query; si.src[1] = key_; si.src[2] = value;
    si.dst[0] = pIsp;  si.dst[1] = pIsp + (size_t)Mrows * K2;
    si.dst[2] = pIsp + 2 * (size_t)Mrows * K2;
    split_in_kernel<<<dim3(3072, 1, 3), 256>>>(si);

    // 2) split + transpose weights
    SplitWArgs sw;
    sw.W[0] = Wq; sw.W[1] = Wk; sw.W[2] = Wv; sw.W[3] = Wo;
    for (int i = 0; i < 4; i++) sw.Wt[i] = pWsp + (size_t)i * Dq * K2;
    split_w_kernel<<<dim3(24, 24, 4), dim3(32, 8)>>>(sw);

    // 3) QKV projections (HMMA)
    TcGemmArgs qkv;
    for (int i = 0; i < 3; i++) {
        qkv.A[i]  = pIsp + (size_t)i * Mrows * K2;
        qkv.Wt[i] = pWsp + (size_t)i * Dq * K2;
    }
    qkv.bias[0] = bq; qkv.bias[1] = bk; qkv.bias[2] = bv;
    qkv.C[0] = pQ;    qkv.C[1] = pK;    qkv.C[2] = pV;
    gemm_tc_kernel<<<dim3(Mrows / 128, Dq / 128, 3), 256>>>(qkv);

    // 4) pre-split K (per-head planes) + transpose-split V
    split_k_kernel<<<3072, 256>>>(pK, pKH, pKL);
    transpose_v_kernel<<<dim3(Sq / 32, HDq / 32, BH), dim3(32, 8)>>>(pV, pVH, pVL);

    // 5) attention (HMMA, pre-split K/V, cp.async double-buffered)
    dim3 ga(Sq / 128, Hq, Bq);
    attn_tc_kernel<<<ga, 256, ATTN3_SMEM>>>(pQ, pKH, pKL, pVH, pVL, pAsp);

    // 6) output projection (HMMA)
    TcGemmArgs og;
    og.A[0] = pAsp; og.Wt[0] = pWsp + 3 * (size_t)Dq * K2;
    og.bias[0] = bo; og.C[0] = out;
    og.A[1] = og.A[2] = pAsp; og.Wt[1] = og.Wt[2] = og.Wt[0];
    og.bias[1] = og.bias[2] = bo; og.C[1] = og.C[2] = og.C[0];
    gemm_tc_kernel<<<dim3(Mrows / 128, Dq / 128, 1), 256>>>(og);
}